// round 4
// baseline (speedup 1.0000x reference)
#include <cuda_runtime.h>
#include <cstdint>
#include <math.h>

#define BB 32
#define TT 256
#define DD 512
#define HH 2048
#define VV 32000
#define BT (BB*TT)          // 8192

// ---------------- scratch (device globals; no allocation allowed) ------------
__device__ float g_ux[BT*HH];          // [B*T, H] input projection      (64 MB)
__device__ float g_h [BT*HH];          // [B*T, H] hidden states fp32    (64 MB)
__device__ float g_hr[BT*HH];          // tf32-rounded copy for V GEMM   (64 MB)
__device__ float g_vw[(size_t)VV*HH];  // tf32-rounded V_w               (262 MB)
__device__ float g_part[4*BB*HH];      // split-K partials for recurrence
__device__ float g_rowloss[BT];

// ======================= Kernel A: ux = C[xb] @ U^T + b ======================
// M=8192, N=2048, K=512.  128x128 block tile, BK=16, 256 thr, 8x8 per thread.
__global__ __launch_bounds__(256) void k_uproj(const int* __restrict__ xb,
                                               const float* __restrict__ Cemb,
                                               const float* __restrict__ Uw,
                                               const float* __restrict__ Ub)
{
    __shared__ float As[16][128];
    __shared__ float Bs[16][128];
    const int bn = blockIdx.x, bm = blockIdx.y;
    const int tid = threadIdx.x;
    const int tx = tid & 15, ty = tid >> 4;

    float acc[8][8];
    #pragma unroll
    for (int i = 0; i < 8; ++i)
        #pragma unroll
        for (int j = 0; j < 8; ++j) acc[i][j] = 0.f;

    for (int c = 0; c < DD/16; ++c) {
        const int k0 = c * 16;
        // load A tile (gather rows via xb), store transposed [k][m]
        #pragma unroll
        for (int it = 0; it < 2; ++it) {
            int idx = tid + it*256;          // 0..511
            int r = idx & 127, q = idx >> 7; // q in 0..3
            int tok = xb[bm*128 + r];
            float4 v = *(const float4*)&Cemb[(size_t)tok*DD + k0 + q*4];
            As[q*4+0][r] = v.x; As[q*4+1][r] = v.y;
            As[q*4+2][r] = v.z; As[q*4+3][r] = v.w;
        }
        // load B tile from U_w [n][k], store transposed [k][n]
        #pragma unroll
        for (int it = 0; it < 2; ++it) {
            int idx = tid + it*256;
            int r = idx & 127, q = idx >> 7;
            float4 v = *(const float4*)&Uw[(size_t)(bn*128 + r)*DD + k0 + q*4];
            Bs[q*4+0][r] = v.x; Bs[q*4+1][r] = v.y;
            Bs[q*4+2][r] = v.z; Bs[q*4+3][r] = v.w;
        }
        __syncthreads();
        #pragma unroll
        for (int k = 0; k < 16; ++k) {
            float a[8], b[8];
            *(float4*)(a)   = *(float4*)&As[k][ty*8];
            *(float4*)(a+4) = *(float4*)&As[k][ty*8+4];
            *(float4*)(b)   = *(float4*)&Bs[k][tx*8];
            *(float4*)(b+4) = *(float4*)&Bs[k][tx*8+4];
            #pragma unroll
            for (int i = 0; i < 8; ++i)
                #pragma unroll
                for (int j = 0; j < 8; ++j) acc[i][j] += a[i]*b[j];
        }
        __syncthreads();
    }
    // epilogue: add bias, store
    const int n0 = bn*128 + tx*8;
    float ub[8];
    #pragma unroll
    for (int j = 0; j < 8; ++j) ub[j] = Ub[n0+j];
    #pragma unroll
    for (int i = 0; i < 8; ++i) {
        size_t m = (size_t)(bm*128 + ty*8 + i);
        float4 o0 = {acc[i][0]+ub[0], acc[i][1]+ub[1], acc[i][2]+ub[2], acc[i][3]+ub[3]};
        float4 o1 = {acc[i][4]+ub[4], acc[i][5]+ub[5], acc[i][6]+ub[6], acc[i][7]+ub[7]};
        *(float4*)&g_ux[m*HH + n0]     = o0;
        *(float4*)&g_ux[m*HH + n0 + 4] = o1;
    }
}

// ================= Kernel B1: recurrence split-K partial GEMM ================
// blocks: 32 col-tiles (64 cols) x 4 K-splits (512 K each). tile 32(b) x 64(c).
__global__ __launch_bounds__(256) void k_rnn_partial(const float* __restrict__ Ww, int t)
{
    __shared__ float Hs[32][36];
    __shared__ float Ws[64][36];
    const int bcol = blockIdx.x & 31;
    const int ks   = blockIdx.x >> 5;
    const int colbase = bcol * 64;
    const int tid = threadIdx.x;
    const int ct = tid & 31, bt = tid >> 5;

    float acc[4][2];
    #pragma unroll
    for (int i = 0; i < 4; ++i) { acc[i][0] = 0.f; acc[i][1] = 0.f; }

    for (int c = 0; c < 16; ++c) {
        const int k0 = ks*512 + c*32;
        {   // H tile: 32 rows x 32 k = 256 float4, 1 per thread
            int r = tid >> 3, q = tid & 7;
            float4 v;
            if (t == 0) v = make_float4(0.1f, 0.1f, 0.1f, 0.1f);
            else        v = *(const float4*)&g_h[((size_t)r*TT + (t-1))*HH + k0 + q*4];
            *(float4*)&Hs[r][q*4] = v;
        }
        #pragma unroll
        for (int it = 0; it < 2; ++it) { // W tile: 64 x 32 = 512 float4
            int idx = tid + it*256;
            int r = idx >> 3, q = idx & 7;
            *(float4*)&Ws[r][q*4] =
                *(const float4*)&Ww[(size_t)(colbase + r)*HH + k0 + q*4];
        }
        __syncthreads();
        #pragma unroll
        for (int kk = 0; kk < 32; kk += 4) {
            float4 w0 = *(float4*)&Ws[ct][kk];
            float4 w1 = *(float4*)&Ws[ct+32][kk];
            #pragma unroll
            for (int i = 0; i < 4; ++i) {
                float4 h = *(float4*)&Hs[bt*4 + i][kk];
                acc[i][0] += h.x*w0.x; acc[i][0] += h.y*w0.y;
                acc[i][0] += h.z*w0.z; acc[i][0] += h.w*w0.w;
                acc[i][1] += h.x*w1.x; acc[i][1] += h.y*w1.y;
                acc[i][1] += h.z*w1.z; acc[i][1] += h.w*w1.w;
            }
        }
        __syncthreads();
    }
    #pragma unroll
    for (int i = 0; i < 4; ++i) {
        int b = bt*4 + i;
        g_part[(ks*BB + b)*HH + colbase + ct]      = acc[i][0];
        g_part[(ks*BB + b)*HH + colbase + ct + 32] = acc[i][1];
    }
}

// ============ Kernel B2: sum partials + ux, tanh, write h / h_tf32 ===========
__global__ __launch_bounds__(256) void k_rnn_finish(int t)
{
    int i = blockIdx.x*256 + threadIdx.x;    // 0..65535
    int b = i >> 11, j = i & 2047;
    float s = g_ux[((size_t)b*TT + t)*HH + j]
            + g_part[i] + g_part[65536 + i] + g_part[2*65536 + i] + g_part[3*65536 + i];
    float h = tanhf(s);
    size_t o = ((size_t)b*TT + t)*HH + j;
    g_h[o] = h;
    float hr;
    asm("cvt.rna.tf32.f32 %0, %1;" : "=f"(hr) : "f"(h));
    g_hr[o] = hr;
}

// ================= pre-round V_w to tf32 (RN) once per launch ================
__global__ __launch_bounds__(256) void k_round_vw(const float* __restrict__ Vw)
{
    size_t i = ((size_t)blockIdx.x*256 + threadIdx.x) * 4;
    float4 v = *(const float4*)&Vw[i];
    float4 o;
    asm("cvt.rna.tf32.f32 %0, %1;" : "=f"(o.x) : "f"(v.x));
    asm("cvt.rna.tf32.f32 %0, %1;" : "=f"(o.y) : "f"(v.y));
    asm("cvt.rna.tf32.f32 %0, %1;" : "=f"(o.z) : "f"(v.z));
    asm("cvt.rna.tf32.f32 %0, %1;" : "=f"(o.w) : "f"(v.w));
    *(float4*)&g_vw[i] = o;
}

// ================= Kernel C: logits = h @ V_w^T + V_b  (tf32 MMA) ============
// M=8192 N=32000 K=2048. Block tile 128x256, BK=16, 8 warps (2x4), warp 64x64.
// smem padded to stride 20 floats (conflict-free frag loads), cp.async 2-stage.
__global__ __launch_bounds__(256, 1) void k_vgemm(const float* __restrict__ Vb,
                                                  float* __restrict__ out)
{
    extern __shared__ float sm[];
    float* As = sm;                 // 2 x 128 x 20
    float* Bs = sm + 2*128*20;      // 2 x 256 x 20

    const int bid = blockIdx.x;                 // 8000 = 64 x 125, swizzled
    const int grp = bid / 1000;                 // 8 m-panels per group
    const int rem = bid % 1000;
    const int bm  = grp*8 + (rem & 7);          // 0..63
    const int bn  = rem >> 3;                   // 0..124

    const int tid = threadIdx.x;
    const int lane = tid & 31, wid = tid >> 5;
    const int wm = (wid >> 2) * 64, wn = (wid & 3) * 64;
    const int gr = lane >> 2, tg = lane & 3;

    const float* Ag = g_hr + (size_t)(bm*128)*HH;
    const float* Bg = g_vw + (size_t)(bn*256)*HH;

    float acc[4][8][4];
    #pragma unroll
    for (int m = 0; m < 4; ++m)
        #pragma unroll
        for (int n = 0; n < 8; ++n)
            #pragma unroll
            for (int q = 0; q < 4; ++q) acc[m][n][q] = 0.f;

    auto issue = [&](int c, int buf) {
        #pragma unroll
        for (int i = 0; i < 2; ++i) {               // A: 512 float4
            int idx = tid + i*256;
            int r = idx >> 2, q = idx & 3;
            unsigned dst = (unsigned)__cvta_generic_to_shared(&As[buf*2560 + r*20 + q*4]);
            const float* src = Ag + (size_t)r*HH + c*16 + q*4;
            asm volatile("cp.async.ca.shared.global [%0], [%1], 16;\n" :: "r"(dst), "l"(src));
        }
        #pragma unroll
        for (int i = 0; i < 4; ++i) {               // B: 1024 float4
            int idx = tid + i*256;
            int r = idx >> 2, q = idx & 3;
            unsigned dst = (unsigned)__cvta_generic_to_shared(&Bs[buf*5120 + r*20 + q*4]);
            const float* src = Bg + (size_t)r*HH + c*16 + q*4;
            asm volatile("cp.async.ca.shared.global [%0], [%1], 16;\n" :: "r"(dst), "l"(src));
        }
    };

    issue(0, 0);
    asm volatile("cp.async.commit_group;\n");
    int buf = 0;
    for (int c = 0; c < HH/16; ++c) {
        if (c + 1 < HH/16) {
            issue(c+1, buf ^ 1);
            asm volatile("cp.async.commit_group;\n");
            asm volatile("cp.async.wait_group 1;\n");
        } else {
            asm volatile("cp.async.wait_group 0;\n");
        }
        __syncthreads();
        const float* A0 = As + buf*2560;
        const float* B0 = Bs + buf*5120;
        #pragma unroll
        for (int ks = 0; ks < 16; ks += 8) {
            unsigned a[4][4], b[8][2];
            #pragma unroll
            for (int mt = 0; mt < 4; ++mt) {
                const float* p = A0 + (wm + mt*16 + gr)*20 + ks + tg;
                a[mt][0] = __float_as_uint(p[0]);
                a[mt][1] = __float_as_uint(p[8*20]);
                a[mt][2] = __float_as_uint(p[4]);
                a[mt][3] = __float_as_uint(p[8*20 + 4]);
            }
            #pragma unroll
            for (int nt = 0; nt < 8; ++nt) {
                const float* p = B0 + (wn + nt*8 + gr)*20 + ks + tg;
                b[nt][0] = __float_as_uint(p[0]);
                b[nt][1] = __float_as_uint(p[4]);
            }
            #pragma unroll
            for (int mt = 0; mt < 4; ++mt)
                #pragma unroll
                for (int nt = 0; nt < 8; ++nt)
                    asm volatile(
                        "mma.sync.aligned.m16n8k8.row.col.f32.tf32.tf32.f32 "
                        "{%0,%1,%2,%3},{%4,%5,%6,%7},{%8,%9},{%0,%1,%2,%3};\n"
                        : "+f"(acc[mt][nt][0]), "+f"(acc[mt][nt][1]),
                          "+f"(acc[mt][nt][2]), "+f"(acc[mt][nt][3])
                        : "r"(a[mt][0]), "r"(a[mt][1]), "r"(a[mt][2]), "r"(a[mt][3]),
                          "r"(b[nt][0]), "r"(b[nt][1]));
        }
        __syncthreads();
        buf ^= 1;
    }

    // epilogue: +bias, store fp32 logits
    #pragma unroll
    for (int mt = 0; mt < 4; ++mt) {
        size_t r0 = (size_t)(bm*128 + wm + mt*16 + gr);
        #pragma unroll
        for (int nt = 0; nt < 8; ++nt) {
            int col = bn*256 + wn + nt*8 + tg*2;
            float b0 = Vb[col], b1 = Vb[col+1];
            float2 v0 = {acc[mt][nt][0] + b0, acc[mt][nt][1] + b1};
            float2 v1 = {acc[mt][nt][2] + b0, acc[mt][nt][3] + b1};
            *(float2*)&out[r0*VV + col]       = v0;
            *(float2*)&out[(r0+8)*VV + col]   = v1;
        }
    }
}

// ================= Kernel D1: per-row logsumexp - logit[target] ==============
__global__ __launch_bounds__(256) void k_rowloss(const float* __restrict__ logits,
                                                 const int* __restrict__ targets)
{
    __shared__ float red[256];
    const int r = blockIdx.x;
    const int tid = threadIdx.x;
    const float* row = logits + (size_t)r*VV;
    const float4* row4 = (const float4*)row;

    float m = -1e30f;
    for (int i = tid; i < VV/4; i += 256) {
        float4 v = row4[i];
        m = fmaxf(m, fmaxf(fmaxf(v.x, v.y), fmaxf(v.z, v.w)));
    }
    red[tid] = m; __syncthreads();
    for (int s = 128; s > 0; s >>= 1) {
        if (tid < s) red[tid] = fmaxf(red[tid], red[tid+s]);
        __syncthreads();
    }
    m = red[0]; __syncthreads();

    float ssum = 0.f;
    for (int i = tid; i < VV/4; i += 256) {
        float4 v = row4[i];
        ssum += __expf(v.x - m) + __expf(v.y - m) + __expf(v.z - m) + __expf(v.w - m);
    }
    red[tid] = ssum; __syncthreads();
    for (int s = 128; s > 0; s >>= 1) {
        if (tid < s) red[tid] += red[tid+s];
        __syncthreads();
    }
    if (tid == 0) {
        float lse = m + logf(red[0]);
        g_rowloss[r] = lse - row[targets[r]];
    }
}

// ================= Kernel D2: mean of row losses -> d_out[last] ==============
__global__ __launch_bounds__(256) void k_loss(float* __restrict__ out, int out_size)
{
    __shared__ float red[256];
    const int tid = threadIdx.x;
    float s = 0.f;
    for (int i = tid; i < BT; i += 256) s += g_rowloss[i];
    red[tid] = s; __syncthreads();
    for (int st = 128; st > 0; st >>= 1) {
        if (tid < st) red[tid] += red[tid+st];
        __syncthreads();
    }
    if (tid == 0) out[(size_t)out_size - 1] = red[0] / (float)BT;
}

// ============================== launch =======================================
extern "C" void kernel_launch(void* const* d_in, const int* in_sizes, int n_in,
                              void* d_out, int out_size)
{
    const int*   xb      = (const int*)  d_in[0];
    const int*   targets = (const int*)  d_in[1];
    const float* Cemb    = (const float*)d_in[2];
    const float* Uw      = (const float*)d_in[3];
    const float* Ub      = (const float*)d_in[4];
    const float* Ww      = (const float*)d_in[5];
    const float* Vw      = (const float*)d_in[6];
    const float* Vb      = (const float*)d_in[7];
    float* out = (float*)d_out;

    // input projection + tf32 pre-rounding of V_w (independent; both up front)
    k_uproj<<<dim3(16, 64), 256>>>(xb, Cemb, Uw, Ub);
    k_round_vw<<<64000, 256>>>(Vw);

    // sequential Elman recurrence: 256 steps, 2 kernels per step
    for (int t = 0; t < TT; ++t) {
        k_rnn_partial<<<128, 256>>>(Ww, t);
        k_rnn_finish<<<256, 256>>>(t);
    }

    // big vocab GEMM on tensor cores (tf32), 60 KB dynamic smem
    cudaFuncSetAttribute((const void*)k_vgemm,
                         cudaFuncAttributeMaxDynamicSharedMemorySize, 64*1024);
    k_vgemm<<<8000, 256, 61440>>>(Vb, out);

    // loss
    k_rowloss<<<BT, 256>>>(out, targets);
    k_loss<<<1, 256>>>(out, out_size);
}

// round 7
// speedup vs baseline: 1.0832x; 1.0832x over previous
#include <cuda_runtime.h>
#include <cstdint>
#include <math.h>

#define BB 32
#define TT 256
#define DD 512
#define HH 2048
#define VV 32000
#define BT (BB*TT)          // 8192

// ---------------- scratch (device globals; no allocation allowed) ------------
__device__ float g_ux[BT*HH];            // [T][B][H] input projection
__device__ float g_hr[BT*HH];            // [B,T,H] tf32-rounded h for V GEMM
__device__ float g_hT[2][HH*BB];         // transposed h double buffer [k][b]
__device__ float g_wT[(size_t)HH*HH];    // W^T: g_wT[k][col]
__device__ float g_vw[(size_t)VV*HH];    // tf32-rounded V_w
__device__ float g_rowloss[BT];

// ---------------- f32x2 packed helpers --------------------------------------
__device__ __forceinline__ unsigned long long pk2(float a, float b) {
    unsigned long long r;
    asm("mov.b64 %0, {%1, %2};" : "=l"(r) : "f"(a), "f"(b));
    return r;
}
__device__ __forceinline__ void fma2(unsigned long long& acc,
                                     unsigned long long a, unsigned long long b) {
    asm("fma.rn.f32x2 %0, %1, %2, %0;" : "+l"(acc) : "l"(a), "l"(b));
}
__device__ __forceinline__ void unpk2(unsigned long long v, float& lo, float& hi) {
    asm("mov.b64 {%0, %1}, %2;" : "=f"(lo), "=f"(hi) : "l"(v));
}

// ======================= Kernel A: ux = C[xb] @ U^T + b ======================
// M=8192, N=2048, K=512. 128x128 tile, BK=16, 256 thr, 8x8/thread.
// Output written in [T][B][H] layout for the recurrence.
__global__ __launch_bounds__(256) void k_uproj(const int* __restrict__ xb,
                                               const float* __restrict__ Cemb,
                                               const float* __restrict__ Uw,
                                               const float* __restrict__ Ub)
{
    __shared__ float As[16][128];
    __shared__ float Bs[16][128];
    const int bn = blockIdx.x, bm = blockIdx.y;
    const int tid = threadIdx.x;
    const int tx = tid & 15, ty = tid >> 4;

    float acc[8][8];
    #pragma unroll
    for (int i = 0; i < 8; ++i)
        #pragma unroll
        for (int j = 0; j < 8; ++j) acc[i][j] = 0.f;

    for (int c = 0; c < DD/16; ++c) {
        const int k0 = c * 16;
        #pragma unroll
        for (int it = 0; it < 2; ++it) {
            int idx = tid + it*256;
            int r = idx & 127, q = idx >> 7;
            int tok = xb[bm*128 + r];
            float4 v = *(const float4*)&Cemb[(size_t)tok*DD + k0 + q*4];
            As[q*4+0][r] = v.x; As[q*4+1][r] = v.y;
            As[q*4+2][r] = v.z; As[q*4+3][r] = v.w;
        }
        #pragma unroll
        for (int it = 0; it < 2; ++it) {
            int idx = tid + it*256;
            int r = idx & 127, q = idx >> 7;
            float4 v = *(const float4*)&Uw[(size_t)(bn*128 + r)*DD + k0 + q*4];
            Bs[q*4+0][r] = v.x; Bs[q*4+1][r] = v.y;
            Bs[q*4+2][r] = v.z; Bs[q*4+3][r] = v.w;
        }
        __syncthreads();
        #pragma unroll
        for (int k = 0; k < 16; ++k) {
            float a[8], b[8];
            *(float4*)(a)   = *(float4*)&As[k][ty*8];
            *(float4*)(a+4) = *(float4*)&As[k][ty*8+4];
            *(float4*)(b)   = *(float4*)&Bs[k][tx*8];
            *(float4*)(b+4) = *(float4*)&Bs[k][tx*8+4];
            #pragma unroll
            for (int i = 0; i < 8; ++i)
                #pragma unroll
                for (int j = 0; j < 8; ++j) acc[i][j] += a[i]*b[j];
        }
        __syncthreads();
    }
    const int n0 = bn*128 + tx*8;
    float ub[8];
    #pragma unroll
    for (int j = 0; j < 8; ++j) ub[j] = Ub[n0+j];
    #pragma unroll
    for (int i = 0; i < 8; ++i) {
        int m = bm*128 + ty*8 + i;       // m = b*TT + t
        int t = m & 255, b = m >> 8;
        size_t dst = ((size_t)t*BB + b)*HH + n0;
        float4 o0 = {acc[i][0]+ub[0], acc[i][1]+ub[1], acc[i][2]+ub[2], acc[i][3]+ub[3]};
        float4 o1 = {acc[i][4]+ub[4], acc[i][5]+ub[5], acc[i][6]+ub[6], acc[i][7]+ub[7]};
        *(float4*)&g_ux[dst]     = o0;
        *(float4*)&g_ux[dst + 4] = o1;
    }
}

// ===================== W transpose: g_wT[k][col] = W[col][k] =================
__global__ __launch_bounds__(256) void k_twT(const float* __restrict__ Ww)
{
    __shared__ float tile[32][33];
    const int bx = blockIdx.x * 32, by = blockIdx.y * 32;
    const int tx = threadIdx.x & 31, ty = threadIdx.x >> 5;  // ty 0..7
    #pragma unroll
    for (int i = 0; i < 4; ++i) {
        int row = by + ty + i*8;                   // col index of W
        tile[ty + i*8][tx] = Ww[(size_t)row*HH + bx + tx];
    }
    __syncthreads();
    #pragma unroll
    for (int i = 0; i < 4; ++i) {
        int k = bx + ty + i*8;
        g_wT[(size_t)k*HH + by + tx] = tile[tx][ty + i*8];
    }
}

// ============== prologue: h0 fill (graph-replay safe) ========================
__global__ __launch_bounds__(256) void k_rnn_init()
{
    int i = blockIdx.x*256 + threadIdx.x;
    g_hT[0][i] = 0.1f;
}

// ================= one Elman timestep: h_t = tanh(ux_t + W h_{t-1}) ==========
// grid 128 x 256 thr. Block owns 16 H-cols over full K=2048 (no cross-block
// split-K; kernel boundary is the only barrier — no spin, no deadlock).
// h_{t-1} staged in smem in 8 chunks of 256 k-rows (cp.async.cg double buffer,
// L1-bypass since h was written by other SMs last step).
// Thread = (c2:8 col-pairs, rg:4 batch-octets, ks:8 k-slices per chunk).
// Inner: 2 cols x 8 batches via packed FFMA2; W^T loads coalesced (float2).
__global__ __launch_bounds__(256, 1) void k_step(int t)
{
    extern __shared__ float sm[];
    float* hs   = sm;            // 2 x [256 k][32 b] = 16384 floats (64 KB)
    float* part = sm + 16384;    // [8][512] = 4096 floats (16 KB)

    const int tid = threadIdx.x;
    const int c2 = tid & 7;
    const int rg = (tid >> 3) & 3;
    const int ks = tid >> 5;                 // warp index = k-slice
    const int cb = blockIdx.x * 16;

    const float4* hsrc = (const float4*)&g_hT[t & 1][0];   // 16384 float4

    // stage chunk 0
    #pragma unroll
    for (int i = 0; i < 8; ++i) {
        int idx = tid + i*256;
        unsigned d = (unsigned)__cvta_generic_to_shared(hs + idx*4);
        asm volatile("cp.async.cg.shared.global [%0], [%1], 16;\n"
                     :: "r"(d), "l"(hsrc + idx));
    }
    asm volatile("cp.async.commit_group;\n");

    unsigned long long a00=0, a01=0, a02=0, a03=0;   // col0 x (b pairs)
    unsigned long long a10=0, a11=0, a12=0, a13=0;   // col1 x (b pairs)

    for (int ch = 0; ch < 8; ++ch) {
        if (ch < 7) {
            float* dst = hs + ((ch+1) & 1)*8192;
            const float4* src = hsrc + (ch+1)*2048;
            #pragma unroll
            for (int i = 0; i < 8; ++i) {
                int idx = tid + i*256;
                unsigned d = (unsigned)__cvta_generic_to_shared(dst + idx*4);
                asm volatile("cp.async.cg.shared.global [%0], [%1], 16;\n"
                             :: "r"(d), "l"(src + idx));
            }
            asm volatile("cp.async.commit_group;\n");
            asm volatile("cp.async.wait_group 1;\n");
        } else {
            asm volatile("cp.async.wait_group 0;\n");
        }
        __syncthreads();

        unsigned hba = (unsigned)__cvta_generic_to_shared(
            hs + (ch & 1)*8192 + (ks*32)*32 + rg*8);
        const float* wp = &g_wT[(size_t)(ch*256 + ks*32)*HH + cb + c2*2];

        #pragma unroll 8
        for (int kl = 0; kl < 32; ++kl) {
            float2 w = *(const float2*)wp;
            wp += HH;
            unsigned long long w0 = pk2(w.x, w.x);
            unsigned long long w1 = pk2(w.y, w.y);
            unsigned long long h01, h23, h45, h67;
            asm("ld.shared.v2.u64 {%0,%1}, [%2];"
                : "=l"(h01), "=l"(h23) : "r"(hba));
            asm("ld.shared.v2.u64 {%0,%1}, [%2];"
                : "=l"(h45), "=l"(h67) : "r"(hba + 16));
            hba += 128;
            fma2(a00, h01, w0); fma2(a01, h23, w0);
            fma2(a02, h45, w0); fma2(a03, h67, w0);
            fma2(a10, h01, w1); fma2(a11, h23, w1);
            fma2(a12, h45, w1); fma2(a13, h67, w1);
        }
        __syncthreads();
    }

    // scatter partials: part[ks][col(0..15)*32 + b]
    {
        float lo, hi;
        float* p0 = &part[ks*512 + (c2*2 + 0)*32 + rg*8];
        float* p1 = &part[ks*512 + (c2*2 + 1)*32 + rg*8];
        unpk2(a00, lo, hi); p0[0] = lo; p0[1] = hi;
        unpk2(a01, lo, hi); p0[2] = lo; p0[3] = hi;
        unpk2(a02, lo, hi); p0[4] = lo; p0[5] = hi;
        unpk2(a03, lo, hi); p0[6] = lo; p0[7] = hi;
        unpk2(a10, lo, hi); p1[0] = lo; p1[1] = hi;
        unpk2(a11, lo, hi); p1[2] = lo; p1[3] = hi;
        unpk2(a12, lo, hi); p1[4] = lo; p1[5] = hi;
        unpk2(a13, lo, hi); p1[6] = lo; p1[7] = hi;
    }
    __syncthreads();

    // each thread finishes 2 outputs: 8-way k-reduce + ux + tanh + stores
    #pragma unroll
    for (int u = 0; u < 2; ++u) {
        int o = tid*2 + u;                 // 0..511
        int c = o >> 5, b = o & 31;
        float s = part[o] + part[512 + o] + part[1024 + o] + part[1536 + o]
                + part[2048 + o] + part[2560 + o] + part[3072 + o] + part[3584 + o];
        s += g_ux[((size_t)t*BB + b)*HH + cb + c];
        float h = tanhf(s);
        g_hT[(t+1) & 1][(size_t)(cb + c)*BB + b] = h;
        float hr; asm("cvt.rna.tf32.f32 %0, %1;" : "=f"(hr) : "f"(h));
        g_hr[((size_t)b*TT + t)*HH + cb + c] = hr;
    }
}

// ================= pre-round V_w to tf32 once per launch =====================
__global__ __launch_bounds__(256) void k_round_vw(const float* __restrict__ Vw)
{
    size_t i = ((size_t)blockIdx.x*256 + threadIdx.x) * 4;
    float4 v = *(const float4*)&Vw[i];
    float4 o;
    asm("cvt.rna.tf32.f32 %0, %1;" : "=f"(o.x) : "f"(v.x));
    asm("cvt.rna.tf32.f32 %0, %1;" : "=f"(o.y) : "f"(v.y));
    asm("cvt.rna.tf32.f32 %0, %1;" : "=f"(o.z) : "f"(v.z));
    asm("cvt.rna.tf32.f32 %0, %1;" : "=f"(o.w) : "f"(v.w));
    *(float4*)&g_vw[i] = o;
}

// ================= Kernel C: logits = h @ V_w^T + V_b  (tf32 MMA) ============
// M=8192 N=32000 K=2048. Block 128x256, BK=16, 8 warps (2x4), warp 64x64.
__global__ __launch_bounds__(256, 1) void k_vgemm(const float* __restrict__ Vb,
                                                  float* __restrict__ out)
{
    extern __shared__ float smv[];
    float* As = smv;                // 2 x 128 x 20
    float* Bs = smv + 2*128*20;     // 2 x 256 x 20

    const int bid = blockIdx.x;
    const int grp = bid / 1000;
    const int rem = bid % 1000;
    const int bm  = grp*8 + (rem & 7);
    const int bn  = rem >> 3;

    const int tid = threadIdx.x;
    const int lane = tid & 31, wid = tid >> 5;
    const int wm = (wid >> 2) * 64, wn = (wid & 3) * 64;
    const int gr = lane >> 2, tg = lane & 3;

    const float* Ag = g_hr + (size_t)(bm*128)*HH;
    const float* Bg = g_vw + (size_t)(bn*256)*HH;

    float acc[4][8][4];
    #pragma unroll
    for (int m = 0; m < 4; ++m)
        #pragma unroll
        for (int n = 0; n < 8; ++n)
            #pragma unroll
            for (int q = 0; q < 4; ++q) acc[m][n][q] = 0.f;

    auto issue = [&](int c, int buf) {
        #pragma unroll
        for (int i = 0; i < 2; ++i) {
            int idx = tid + i*256;
            int r = idx >> 2, q = idx & 3;
            unsigned dst = (unsigned)__cvta_generic_to_shared(&As[buf*2560 + r*20 + q*4]);
            const float* src = Ag + (size_t)r*HH + c*16 + q*4;
            asm volatile("cp.async.ca.shared.global [%0], [%1], 16;\n" :: "r"(dst), "l"(src));
        }
        #pragma unroll
        for (int i = 0; i < 4; ++i) {
            int idx = tid + i*256;
            int r = idx >> 2, q = idx & 3;
            unsigned dst = (unsigned)__cvta_generic_to_shared(&Bs[buf*5120 + r*20 + q*4]);
            const float* src = Bg + (size_t)r*HH + c*16 + q*4;
            asm volatile("cp.async.ca.shared.global [%0], [%1], 16;\n" :: "r"(dst), "l"(src));
        }
    };

    issue(0, 0);
    asm volatile("cp.async.commit_group;\n");
    int buf = 0;
    for (int c = 0; c < HH/16; ++c) {
        if (c + 1 < HH/16) {
            issue(c+1, buf ^ 1);
            asm volatile("cp.async.commit_group;\n");
            asm volatile("cp.async.wait_group 1;\n");
        } else {
            asm volatile("cp.async.wait_group 0;\n");
        }
        __syncthreads();
        const float* A0 = As + buf*2560;
        const float* B0 = Bs + buf*5120;
        #pragma unroll
        for (int kq = 0; kq < 16; kq += 8) {
            unsigned a[4][4], b[8][2];
            #pragma unroll
            for (int mt = 0; mt < 4; ++mt) {
                const float* p = A0 + (wm + mt*16 + gr)*20 + kq + tg;
                a[mt][0] = __float_as_uint(p[0]);
                a[mt][1] = __float_as_uint(p[8*20]);
                a[mt][2] = __float_as_uint(p[4]);
                a[mt][3] = __float_as_uint(p[8*20 + 4]);
            }
            #pragma unroll
            for (int nt = 0; nt < 8; ++nt) {
                const float* p = B0 + (wn + nt*8 + gr)*20 + kq + tg;
                b[nt][0] = __float_as_uint(p[0]);
                b[nt][1] = __float_as_uint(p[4]);
            }
            #pragma unroll
            for (int mt = 0; mt < 4; ++mt)
                #pragma unroll
                for (int nt = 0; nt < 8; ++nt)
                    asm volatile(
                        "mma.sync.aligned.m16n8k8.row.col.f32.tf32.tf32.f32 "
                        "{%0,%1,%2,%3},{%4,%5,%6,%7},{%8,%9},{%0,%1,%2,%3};\n"
                        : "+f"(acc[mt][nt][0]), "+f"(acc[mt][nt][1]),
                          "+f"(acc[mt][nt][2]), "+f"(acc[mt][nt][3])
                        : "r"(a[mt][0]), "r"(a[mt][1]), "r"(a[mt][2]), "r"(a[mt][3]),
                          "r"(b[nt][0]), "r"(b[nt][1]));
        }
        __syncthreads();
        buf ^= 1;
    }

    #pragma unroll
    for (int mt = 0; mt < 4; ++mt) {
        size_t r0 = (size_t)(bm*128 + wm + mt*16 + gr);
        #pragma unroll
        for (int nt = 0; nt < 8; ++nt) {
            int col = bn*256 + wn + nt*8 + tg*2;
            float b0 = Vb[col], b1 = Vb[col+1];
            float2 v0 = {acc[mt][nt][0] + b0, acc[mt][nt][1] + b1};
            float2 v1 = {acc[mt][nt][2] + b0, acc[mt][nt][3] + b1};
            *(float2*)&out[r0*VV + col]       = v0;
            *(float2*)&out[(r0+8)*VV + col]   = v1;
        }
    }
}

// ================= Kernel D1: single-pass online log-softmax loss ============
__global__ __launch_bounds__(256) void k_rowloss(const float* __restrict__ logits,
                                                 const int* __restrict__ targets)
{
    __shared__ float smx[256], ssm[256];
    const int r = blockIdx.x;
    const int tid = threadIdx.x;
    const float4* row4 = (const float4*)(logits + (size_t)r*VV);

    float m = -1e30f, s = 0.f;
    for (int i = tid; i < VV/4; i += 256) {
        float4 v = row4[i];
        float m2 = fmaxf(fmaxf(v.x, v.y), fmaxf(v.z, v.w));
        if (m2 > m) { s *= __expf(m - m2); m = m2; }
        s += __expf(v.x - m) + __expf(v.y - m) + __expf(v.z - m) + __expf(v.w - m);
    }
    smx[tid] = m; ssm[tid] = s; __syncthreads();
    for (int st = 128; st > 0; st >>= 1) {
        if (tid < st) {
            float ma = smx[tid], mb = smx[tid+st];
            float sa = ssm[tid], sb = ssm[tid+st];
            float nm = fmaxf(ma, mb);
            smx[tid] = nm;
            ssm[tid] = sa*__expf(ma - nm) + sb*__expf(mb - nm);
        }
        __syncthreads();
    }
    if (tid == 0) {
        g_rowloss[r] = smx[0] + logf(ssm[0]) - logits[(size_t)r*VV + targets[r]];
    }
}

// ================= Kernel D2: mean of row losses -> d_out[last] ==============
__global__ __launch_bounds__(256) void k_loss(float* __restrict__ out, int out_size)
{
    __shared__ float red[256];
    const int tid = threadIdx.x;
    float s = 0.f;
    for (int i = tid; i < BT; i += 256) s += g_rowloss[i];
    red[tid] = s; __syncthreads();
    for (int st = 128; st > 0; st >>= 1) {
        if (tid < st) red[tid] += red[tid+st];
        __syncthreads();
    }
    if (tid == 0) out[(size_t)out_size - 1] = red[0] / (float)BT;
}

// ============================== launch =======================================
extern "C" void kernel_launch(void* const* d_in, const int* in_sizes, int n_in,
                              void* d_out, int out_size)
{
    const int*   xb      = (const int*)  d_in[0];
    const int*   targets = (const int*)  d_in[1];
    const float* Cemb    = (const float*)d_in[2];
    const float* Uw      = (const float*)d_in[3];
    const float* Ub      = (const float*)d_in[4];
    const float* Ww      = (const float*)d_in[5];
    const float* Vw      = (const float*)d_in[6];
    const float* Vb      = (const float*)d_in[7];
    float* out = (float*)d_out;

    // independent preprocessing
    k_uproj<<<dim3(16, 64), 256>>>(xb, Cemb, Uw, Ub);
    k_round_vw<<<64000, 256>>>(Vw);
    k_twT<<<dim3(64, 64), 256>>>(Ww);
    k_rnn_init<<<256, 256>>>();

    // recurrence: one kernel per step (kernel boundary = barrier; no spin)
    cudaFuncSetAttribute((const void*)k_step,
                         cudaFuncAttributeMaxDynamicSharedMemorySize, 81920);
    for (int t = 0; t < TT; ++t) {
        k_step<<<128, 256, 81920>>>(t);
    }

    // big vocab GEMM on tensor cores (tf32)
    cudaFuncSetAttribute((const void*)k_vgemm,
                         cudaFuncAttributeMaxDynamicSharedMemorySize, 64*1024);
    k_vgemm<<<8000, 256, 61440>>>(Vb, out);

    // loss
    k_rowloss<<<BT, 256>>>(out, targets);
    k_loss<<<1, 256>>>(out, out_size);
}

// round 9
// speedup vs baseline: 1.2236x; 1.1296x over previous
#include <cuda_runtime.h>
#include <cstdint>
#include <math.h>

#define BB 32
#define TT 256
#define DD 512
#define HH 2048
#define VV 32000
#define BT (BB*TT)          // 8192

// ---------------- scratch (device globals; no allocation allowed) ------------
__device__ float g_ux[BT*HH];            // [T][B][H] input projection
__device__ float g_hr[BT*HH];            // [B,T,H] tf32 h, K-permuted in 16-blk
__device__ float g_hT[2][HH*BB];         // transposed h double buffer [k][b]
__device__ float g_wP[(size_t)HH*HH];    // W packed: [blk][k][16 cols]
__device__ float g_vw[(size_t)VV*HH];    // tf32 V_w, K-permuted in 16-blk
__device__ float g_rowloss[BT];

// ---------------- f32x2 packed helpers --------------------------------------
__device__ __forceinline__ unsigned long long pk2(float a, float b) {
    unsigned long long r;
    asm("mov.b64 %0, {%1, %2};" : "=l"(r) : "f"(a), "f"(b));
    return r;
}
__device__ __forceinline__ void fma2(unsigned long long& acc,
                                     unsigned long long a, unsigned long long b) {
    asm("fma.rn.f32x2 %0, %1, %2, %0;" : "+l"(acc) : "l"(a), "l"(b));
}
__device__ __forceinline__ void unpk2(unsigned long long v, float& lo, float& hi) {
    asm("mov.b64 {%0, %1}, %2;" : "=f"(lo), "=f"(hi) : "l"(v));
}

// ======================= Kernel A: ux = C[xb] @ U^T + b ======================
__global__ __launch_bounds__(256) void k_uproj(const int* __restrict__ xb,
                                               const float* __restrict__ Cemb,
                                               const float* __restrict__ Uw,
                                               const float* __restrict__ Ub)
{
    __shared__ float As[16][128];
    __shared__ float Bs[16][128];
    const int bn = blockIdx.x, bm = blockIdx.y;
    const int tid = threadIdx.x;
    const int tx = tid & 15, ty = tid >> 4;

    float acc[8][8];
    #pragma unroll
    for (int i = 0; i < 8; ++i)
        #pragma unroll
        for (int j = 0; j < 8; ++j) acc[i][j] = 0.f;

    for (int c = 0; c < DD/16; ++c) {
        const int k0 = c * 16;
        #pragma unroll
        for (int it = 0; it < 2; ++it) {
            int idx = tid + it*256;
            int r = idx & 127, q = idx >> 7;
            int tok = xb[bm*128 + r];
            float4 v = *(const float4*)&Cemb[(size_t)tok*DD + k0 + q*4];
            As[q*4+0][r] = v.x; As[q*4+1][r] = v.y;
            As[q*4+2][r] = v.z; As[q*4+3][r] = v.w;
        }
        #pragma unroll
        for (int it = 0; it < 2; ++it) {
            int idx = tid + it*256;
            int r = idx & 127, q = idx >> 7;
            float4 v = *(const float4*)&Uw[(size_t)(bn*128 + r)*DD + k0 + q*4];
            Bs[q*4+0][r] = v.x; Bs[q*4+1][r] = v.y;
            Bs[q*4+2][r] = v.z; Bs[q*4+3][r] = v.w;
        }
        __syncthreads();
        #pragma unroll
        for (int k = 0; k < 16; ++k) {
            float a[8], b[8];
            *(float4*)(a)   = *(float4*)&As[k][ty*8];
            *(float4*)(a+4) = *(float4*)&As[k][ty*8+4];
            *(float4*)(b)   = *(float4*)&Bs[k][tx*8];
            *(float4*)(b+4) = *(float4*)&Bs[k][tx*8+4];
            #pragma unroll
            for (int i = 0; i < 8; ++i)
                #pragma unroll
                for (int j = 0; j < 8; ++j) acc[i][j] += a[i]*b[j];
        }
        __syncthreads();
    }
    const int n0 = bn*128 + tx*8;
    float ub[8];
    #pragma unroll
    for (int j = 0; j < 8; ++j) ub[j] = Ub[n0+j];
    #pragma unroll
    for (int i = 0; i < 8; ++i) {
        int m = bm*128 + ty*8 + i;       // m = b*TT + t
        int t = m & 255, b = m >> 8;
        size_t dst = ((size_t)t*BB + b)*HH + n0;
        float4 o0 = {acc[i][0]+ub[0], acc[i][1]+ub[1], acc[i][2]+ub[2], acc[i][3]+ub[3]};
        float4 o1 = {acc[i][4]+ub[4], acc[i][5]+ub[5], acc[i][6]+ub[6], acc[i][7]+ub[7]};
        *(float4*)&g_ux[dst]     = o0;
        *(float4*)&g_ux[dst + 4] = o1;
    }
}

// ============ pack W for the recurrence: g_wP[blk][k][c16] = W[blk*16+c][k] ==
__global__ __launch_bounds__(512) void k_packW(const float* __restrict__ Ww)
{
    __shared__ float tile[32][17];
    const int bx = blockIdx.x;           // k-tile (0..63)
    const int by = blockIdx.y;           // col-block (0..127)
    const int tid = threadIdx.x;
    {
        int c = tid >> 5, kk = tid & 31;
        tile[kk][c] = Ww[(size_t)(by*16 + c)*HH + bx*32 + kk];
    }
    __syncthreads();
    {
        int kk = tid >> 4, c = tid & 15;
        g_wP[(size_t)by*(HH*16) + (size_t)(bx*32 + kk)*16 + c] = tile[kk][c];
    }
}

// ===== pre-round V_w to tf32, store K-permuted within 16-blocks ==============
// slot(k) = base16 + (k&3)*4 + ((k>>2)&3). Thread handles 4 consecutive k.
__global__ __launch_bounds__(256) void k_round_vw(const float* __restrict__ Vw)
{
    size_t i = ((size_t)blockIdx.x*256 + threadIdx.x) * 4;
    float4 v = *(const float4*)&Vw[i];
    float4 o;
    asm("cvt.rna.tf32.f32 %0, %1;" : "=f"(o.x) : "f"(v.x));
    asm("cvt.rna.tf32.f32 %0, %1;" : "=f"(o.y) : "f"(v.y));
    asm("cvt.rna.tf32.f32 %0, %1;" : "=f"(o.z) : "f"(v.z));
    asm("cvt.rna.tf32.f32 %0, %1;" : "=f"(o.w) : "f"(v.w));
    size_t base16 = i & ~(size_t)15;
    size_t q = (i >> 2) & 3;
    g_vw[base16 + q + 0]  = o.x;
    g_vw[base16 + q + 4]  = o.y;
    g_vw[base16 + q + 8]  = o.z;
    g_vw[base16 + q + 12] = o.w;
}

// ============== prologue: h0 fill (graph-replay safe) ========================
__global__ __launch_bounds__(256) void k_rnn_init()
{
    int i = blockIdx.x*256 + threadIdx.x;
    g_hT[0][i] = 0.1f;
}

// ================= one Elman timestep: h_t = tanh(ux_t + W h_{t-1}) ==========
// grid 128 x 256 thr. Block owns 16 H-cols over full K=2048; W streams 64B-
// contiguous per warp per k from the packed layout (no strided latency chain).
__global__ __launch_bounds__(256, 1) void k_step(int t)
{
    extern __shared__ float sm[];
    float* hs   = sm;            // 2 x [256 k][32 b] = 16384 floats (64 KB)
    float* part = sm + 16384;    // [8][512] = 4096 floats (16 KB)

    const int tid = threadIdx.x;
    const int c2 = tid & 7;
    const int rg = (tid >> 3) & 3;
    const int ks = tid >> 5;                 // warp index = k-slice
    const int cb = blockIdx.x * 16;

    const float4* hsrc = (const float4*)&g_hT[t & 1][0];   // 16384 float4

    // stage chunk 0
    #pragma unroll
    for (int i = 0; i < 8; ++i) {
        int idx = tid + i*256;
        unsigned d = (unsigned)__cvta_generic_to_shared(hs + idx*4);
        asm volatile("cp.async.cg.shared.global [%0], [%1], 16;\n"
                     :: "r"(d), "l"(hsrc + idx));
    }
    asm volatile("cp.async.commit_group;\n");

    unsigned long long a00=0, a01=0, a02=0, a03=0;   // col0 x (b pairs)
    unsigned long long a10=0, a11=0, a12=0, a13=0;   // col1 x (b pairs)

    for (int ch = 0; ch < 8; ++ch) {
        if (ch < 7) {
            float* dst = hs + ((ch+1) & 1)*8192;
            const float4* src = hsrc + (ch+1)*2048;
            #pragma unroll
            for (int i = 0; i < 8; ++i) {
                int idx = tid + i*256;
                unsigned d = (unsigned)__cvta_generic_to_shared(dst + idx*4);
                asm volatile("cp.async.cg.shared.global [%0], [%1], 16;\n"
                             :: "r"(d), "l"(src + idx));
            }
            asm volatile("cp.async.commit_group;\n");
            asm volatile("cp.async.wait_group 1;\n");
        } else {
            asm volatile("cp.async.wait_group 0;\n");
        }
        __syncthreads();

        unsigned hba = (unsigned)__cvta_generic_to_shared(
            hs + (ch & 1)*8192 + (ks*32)*32 + rg*8);
        const float* wp = g_wP + (size_t)blockIdx.x*(HH*16)
                        + (size_t)(ch*256 + ks*32)*16 + c2*2;

        #pragma unroll 8
        for (int kl = 0; kl < 32; ++kl) {
            float2 w = *(const float2*)wp;
            wp += 16;
            unsigned long long w0 = pk2(w.x, w.x);
            unsigned long long w1 = pk2(w.y, w.y);
            unsigned long long h01, h23, h45, h67;
            asm("ld.shared.v2.u64 {%0,%1}, [%2];"
                : "=l"(h01), "=l"(h23) : "r"(hba));
            asm("ld.shared.v2.u64 {%0,%1}, [%2];"
                : "=l"(h45), "=l"(h67) : "r"(hba + 16));
            hba += 128;
            fma2(a00, h01, w0); fma2(a01, h23, w0);
            fma2(a02, h45, w0); fma2(a03, h67, w0);
            fma2(a10, h01, w1); fma2(a11, h23, w1);
            fma2(a12, h45, w1); fma2(a13, h67, w1);
        }
        __syncthreads();
    }

    // scatter partials: part[ks][col(0..15)*32 + b]
    {
        float lo, hi;
        float* p0 = &part[ks*512 + (c2*2 + 0)*32 + rg*8];
        float* p1 = &part[ks*512 + (c2*2 + 1)*32 + rg*8];
        unpk2(a00, lo, hi); p0[0] = lo; p0[1] = hi;
        unpk2(a01, lo, hi); p0[2] = lo; p0[3] = hi;
        unpk2(a02, lo, hi); p0[4] = lo; p0[5] = hi;
        unpk2(a03, lo, hi); p0[6] = lo; p0[7] = hi;
        unpk2(a10, lo, hi); p1[0] = lo; p1[1] = hi;
        unpk2(a11, lo, hi); p1[2] = lo; p1[3] = hi;
        unpk2(a12, lo, hi); p1[4] = lo; p1[5] = hi;
        unpk2(a13, lo, hi); p1[6] = lo; p1[7] = hi;
    }
    __syncthreads();

    // each thread finishes 2 outputs: 8-way k-reduce + ux + tanh + stores
    #pragma unroll
    for (int u = 0; u < 2; ++u) {
        int o = tid*2 + u;                 // 0..511
        int c = o >> 5, b = o & 31;
        float s = part[o] + part[512 + o] + part[1024 + o] + part[1536 + o]
                + part[2048 + o] + part[2560 + o] + part[3072 + o] + part[3584 + o];
        s += g_ux[((size_t)t*BB + b)*HH + cb + c];
        float h = tanhf(s);
        g_hT[(t+1) & 1][(size_t)(cb + c)*BB + b] = h;     // normal order
        float hr; asm("cvt.rna.tf32.f32 %0, %1;" : "=f"(hr) : "f"(h));
        int permc = ((c & 3) << 2) | (c >> 2);            // K-permuted for GEMM
        g_hr[((size_t)b*TT + t)*HH + cb + permc] = hr;
    }
}

// ================= Kernel C: logits = h @ V_w^T + V_b  (tf32 MMA) ============
// M=8192 N=32000 K=2048. Block 128x256, BK=32, 8 warps (2x4), warp 64x64.
// K is pre-permuted in 16-blocks in BOTH g_hr and g_vw, so every thread's
// fragment (k = tg, tg+4, tg+8, tg+12) is CONTIGUOUS -> all frag loads are
// conflict-free LDS.128, smem rows stride 16 (no padding). 3-stage cp.async.
#define VSTAGE 12288    // floats per stage: A 128x32 (4096) + B 256x32 (8192)
__global__ __launch_bounds__(256, 1) void k_vgemm(const float* __restrict__ Vb,
                                                  float* __restrict__ out)
{
    extern __shared__ float smv[];

    const int bid = blockIdx.x;                 // 8000 = 8 grp x (8 bm x 125 bn)
    const int grp = bid / 1000;
    const int rem = bid % 1000;
    const int bm  = grp*8 + (rem & 7);          // 0..63
    const int bn  = rem >> 3;                   // 0..124

    const int tid = threadIdx.x;
    const int lane = tid & 31, wid = tid >> 5;
    const int wm = (wid >> 2) * 64, wn = (wid & 3) * 64;
    const int gr = lane >> 2, tg = lane & 3;

    const float* Ag = g_hr + (size_t)(bm*128)*HH;
    const float* Bg = g_vw + (size_t)(bn*256)*HH;

    float acc[4][8][4];
    #pragma unroll
    for (int m = 0; m < 4; ++m)
        #pragma unroll
        for (int n = 0; n < 8; ++n)
            #pragma unroll
            for (int q = 0; q < 4; ++q) acc[m][n][q] = 0.f;

    auto stage_load = [&](int c, int s) {
        float* As = smv + s*VSTAGE;
        float* Bs = As + 4096;
        #pragma unroll
        for (int i = 0; i < 4; ++i) {             // A: 1024 x 16B
            int o = tid + i*256;
            int kg = o >> 9, row = (o >> 2) & 127, q = o & 3;
            unsigned d = (unsigned)__cvta_generic_to_shared(As + o*4);
            const float* src = Ag + (size_t)row*HH + c*32 + kg*16 + q*4;
            asm volatile("cp.async.cg.shared.global [%0], [%1], 16;\n"
                         :: "r"(d), "l"(src));
        }
        #pragma unroll
        for (int i = 0; i < 8; ++i) {             // B: 2048 x 16B
            int o = tid + i*256;
            int kg = o >> 10, row = (o >> 2) & 255, q = o & 3;
            unsigned d = (unsigned)__cvta_generic_to_shared(Bs + o*4);
            const float* src = Bg + (size_t)row*HH + c*32 + kg*16 + q*4;
            asm volatile("cp.async.cg.shared.global [%0], [%1], 16;\n"
                         :: "r"(d), "l"(src));
        }
        asm volatile("cp.async.commit_group;\n");
    };

    stage_load(0, 0);
    stage_load(1, 1);

    int sc = 0, sl = 2;
    const int NCH = HH/32;                        // 64 chunks
    for (int c = 0; c < NCH; ++c) {
        if (c < NCH-1) asm volatile("cp.async.wait_group 1;\n");
        else           asm volatile("cp.async.wait_group 0;\n");
        __syncthreads();
        if (c + 2 < NCH) {
            stage_load(c + 2, sl);
            sl = (sl == 2) ? 0 : sl + 1;
        }

        const float* As = smv + sc*VSTAGE;
        const float* Bs = As + 4096;
        #pragma unroll
        for (int kg = 0; kg < 2; ++kg) {
            float4 af[4][2]; float4 bf[8];
            #pragma unroll
            for (int mt = 0; mt < 4; ++mt) {
                af[mt][0] = *(const float4*)&As[(kg*128 + wm + mt*16 + gr)*16 + tg*4];
                af[mt][1] = *(const float4*)&As[(kg*128 + wm + mt*16 + 8 + gr)*16 + tg*4];
            }
            #pragma unroll
            for (int nt = 0; nt < 8; ++nt)
                bf[nt] = *(const float4*)&Bs[(kg*256 + wn + nt*8 + gr)*16 + tg*4];

            #pragma unroll
            for (int mt = 0; mt < 4; ++mt)
                #pragma unroll
                for (int nt = 0; nt < 8; ++nt) {
                    asm volatile(
                        "mma.sync.aligned.m16n8k8.row.col.f32.tf32.tf32.f32 "
                        "{%0,%1,%2,%3},{%4,%5,%6,%7},{%8,%9},{%0,%1,%2,%3};\n"
                        : "+f"(acc[mt][nt][0]), "+f"(acc[mt][nt][1]),
                          "+f"(acc[mt][nt][2]), "+f"(acc[mt][nt][3])
                        : "r"(__float_as_uint(af[mt][0].x)), "r"(__float_as_uint(af[mt][1].x)),
                          "r"(__float_as_uint(af[mt][0].y)), "r"(__float_as_uint(af[mt][1].y)),
                          "r"(__float_as_uint(bf[nt].x)),    "r"(__float_as_uint(bf[nt].y)));
                    asm volatile(
                        "mma.sync.aligned.m16n8k8.row.col.f32.tf32.tf32.f32 "
                        "{%0,%1,%2,%3},{%4,%5,%6,%7},{%8,%9},{%0,%1,%2,%3};\n"
                        : "+f"(acc[mt][nt][0]), "+f"(acc[mt][nt][1]),
                          "+f"(acc[mt][nt][2]), "+f"(acc[mt][nt][3])
                        : "r"(__float_as_uint(af[mt][0].z)), "r"(__float_as_uint(af[mt][1].z)),
                          "r"(__float_as_uint(af[mt][0].w)), "r"(__float_as_uint(af[mt][1].w)),
                          "r"(__float_as_uint(bf[nt].z)),    "r"(__float_as_uint(bf[nt].w)));
                }
        }
        sc = (sc == 2) ? 0 : sc + 1;
    }

    // epilogue: +bias, store fp32 logits
    #pragma unroll
    for (int mt = 0; mt < 4; ++mt) {
        size_t r0 = (size_t)(bm*128 + wm + mt*16 + gr);
        #pragma unroll
        for (int nt = 0; nt < 8; ++nt) {
            int col = bn*256 + wn + nt*8 + tg*2;
            float b0 = Vb[col], b1 = Vb[col+1];
            float2 v0 = {acc[mt][nt][0] + b0, acc[mt][nt][1] + b1};
            float2 v1 = {acc[mt][nt][2] + b0, acc[mt][nt][3] + b1};
            *(float2*)&out[r0*VV + col]       = v0;
            *(float2*)&out[(r0+8)*VV + col]   = v1;
        }
    }
}

// ================= Kernel D1: single-pass online log-softmax loss ============
__global__ __launch_bounds__(256) void k_rowloss(const float* __restrict__ logits,
                                                 const int* __restrict__ targets)
{
    __shared__ float smx[256], ssm[256];
    const int r = blockIdx.x;
    const int tid = threadIdx.x;
    const float4* row4 = (const float4*)(logits + (size_t)r*VV);

    float m = -1e30f, s = 0.f;
    for (int i = tid; i < VV/4; i += 256) {
        float4 v = row4[i];
        float m2 = fmaxf(fmaxf(v.x, v.y), fmaxf(v.z, v.w));
        if (m2 > m) { s *= __expf(m - m2); m = m2; }
        s += __expf(v.x - m) + __expf(v.y - m) + __expf(v.z - m) + __expf(v.w - m);
    }
    smx[tid] = m; ssm[tid] = s; __syncthreads();
    for (int st = 128; st > 0; st >>= 1) {
        if (tid < st) {
            float ma = smx[tid], mb = smx[tid+st];
            float sa = ssm[tid], sb = ssm[tid+st];
            float nm = fmaxf(ma, mb);
            smx[tid] = nm;
            ssm[tid] = sa*__expf(ma - nm) + sb*__expf(mb - nm);
        }
        __syncthreads();
    }
    if (tid == 0) {
        g_rowloss[r] = smx[0] + logf(ssm[0]) - logits[(size_t)r*VV + targets[r]];
    }
}

// ================= Kernel D2: mean of row losses -> d_out[last] ==============
__global__ __launch_bounds__(256) void k_loss(float* __restrict__ out, int out_size)
{
    __shared__ float red[256];
    const int tid = threadIdx.x;
    float s = 0.f;
    for (int i = tid; i < BT; i += 256) s += g_rowloss[i];
    red[tid] = s; __syncthreads();
    for (int st = 128; st > 0; st >>= 1) {
        if (tid < st) red[tid] += red[tid+st];
        __syncthreads();
    }
    if (tid == 0) out[(size_t)out_size - 1] = red[0] / (float)BT;
}

// ============================== launch =======================================
extern "C" void kernel_launch(void* const* d_in, const int* in_sizes, int n_in,
                              void* d_out, int out_size)
{
    const int*   xb      = (const int*)  d_in[0];
    const int*   targets = (const int*)  d_in[1];
    const float* Cemb    = (const float*)d_in[2];
    const float* Uw      = (const float*)d_in[3];
    const float* Ub      = (const float*)d_in[4];
    const float* Ww      = (const float*)d_in[5];
    const float* Vw      = (const float*)d_in[6];
    const float* Vb      = (const float*)d_in[7];
    float* out = (float*)d_out;

    // independent preprocessing
    k_uproj<<<dim3(16, 64), 256>>>(xb, Cemb, Uw, Ub);
    k_round_vw<<<64000, 256>>>(Vw);
    k_packW<<<dim3(64, 128), 512>>>(Ww);
    k_rnn_init<<<256, 256>>>();

    // recurrence: one kernel per step (kernel boundary = barrier; no spin)
    cudaFuncSetAttribute((const void*)k_step,
                         cudaFuncAttributeMaxDynamicSharedMemorySize, 81920);
    for (int t = 0; t < TT; ++t) {
        k_step<<<128, 256, 81920>>>(t);
    }

    // big vocab GEMM on tensor cores (tf32, vectorized frag loads, 3-stage)
    cudaFuncSetAttribute((const void*)k_vgemm,
                         cudaFuncAttributeMaxDynamicSharedMemorySize, 3*VSTAGE*4);
    k_vgemm<<<8000, 256, 3*VSTAGE*4>>>(Vb, out);

    // loss
    k_rowloss<<<BT, 256>>>(out, targets);
    k_loss<<<1, 256>>>(out, out_size);
}

// round 10
// speedup vs baseline: 1.2259x; 1.0019x over previous
#include <cuda_runtime.h>
#include <cstdint>
#include <math.h>

#define BB 32
#define TT 256
#define DD 512
#define HH 2048
#define VV 32000
#define BT (BB*TT)          // 8192

// ---------------- scratch (device globals; no allocation allowed) ------------
__device__ float g_ux[BT*HH];            // [T][B][H] input projection
__device__ float g_hr[BT*HH];            // [B,T,H] tf32 h, K-permuted in 16-blk
__device__ float g_hT[2][HH*BB];         // transposed h double buffer [k][b]
__device__ float g_wP[(size_t)HH*HH];    // W packed: [blk][k][16 cols]
__device__ float g_vw[(size_t)VV*HH];    // tf32 V_w, K-permuted in 16-blk
__device__ float g_rowloss[BT];

// ---------------- f32x2 packed helpers --------------------------------------
__device__ __forceinline__ unsigned long long pk2(float a, float b) {
    unsigned long long r;
    asm("mov.b64 %0, {%1, %2};" : "=l"(r) : "f"(a), "f"(b));
    return r;
}
__device__ __forceinline__ void fma2(unsigned long long& acc,
                                     unsigned long long a, unsigned long long b) {
    asm("fma.rn.f32x2 %0, %1, %2, %0;" : "+l"(acc) : "l"(a), "l"(b));
}
__device__ __forceinline__ void unpk2(unsigned long long v, float& lo, float& hi) {
    asm("mov.b64 {%0, %1}, %2;" : "=f"(lo), "=f"(hi) : "l"(v));
}

// ======================= Kernel A: ux = C[xb] @ U^T + b ======================
__global__ __launch_bounds__(256) void k_uproj(const int* __restrict__ xb,
                                               const float* __restrict__ Cemb,
                                               const float* __restrict__ Uw,
                                               const float* __restrict__ Ub)
{
    __shared__ float As[16][128];
    __shared__ float Bs[16][128];
    const int bn = blockIdx.x, bm = blockIdx.y;
    const int tid = threadIdx.x;
    const int tx = tid & 15, ty = tid >> 4;

    float acc[8][8];
    #pragma unroll
    for (int i = 0; i < 8; ++i)
        #pragma unroll
        for (int j = 0; j < 8; ++j) acc[i][j] = 0.f;

    for (int c = 0; c < DD/16; ++c) {
        const int k0 = c * 16;
        #pragma unroll
        for (int it = 0; it < 2; ++it) {
            int idx = tid + it*256;
            int r = idx & 127, q = idx >> 7;
            int tok = xb[bm*128 + r];
            float4 v = *(const float4*)&Cemb[(size_t)tok*DD + k0 + q*4];
            As[q*4+0][r] = v.x; As[q*4+1][r] = v.y;
            As[q*4+2][r] = v.z; As[q*4+3][r] = v.w;
        }
        #pragma unroll
        for (int it = 0; it < 2; ++it) {
            int idx = tid + it*256;
            int r = idx & 127, q = idx >> 7;
            float4 v = *(const float4*)&Uw[(size_t)(bn*128 + r)*DD + k0 + q*4];
            Bs[q*4+0][r] = v.x; Bs[q*4+1][r] = v.y;
            Bs[q*4+2][r] = v.z; Bs[q*4+3][r] = v.w;
        }
        __syncthreads();
        #pragma unroll
        for (int k = 0; k < 16; ++k) {
            float a[8], b[8];
            *(float4*)(a)   = *(float4*)&As[k][ty*8];
            *(float4*)(a+4) = *(float4*)&As[k][ty*8+4];
            *(float4*)(b)   = *(float4*)&Bs[k][tx*8];
            *(float4*)(b+4) = *(float4*)&Bs[k][tx*8+4];
            #pragma unroll
            for (int i = 0; i < 8; ++i)
                #pragma unroll
                for (int j = 0; j < 8; ++j) acc[i][j] += a[i]*b[j];
        }
        __syncthreads();
    }
    const int n0 = bn*128 + tx*8;
    float ub[8];
    #pragma unroll
    for (int j = 0; j < 8; ++j) ub[j] = Ub[n0+j];
    #pragma unroll
    for (int i = 0; i < 8; ++i) {
        int m = bm*128 + ty*8 + i;       // m = b*TT + t
        int t = m & 255, b = m >> 8;
        size_t dst = ((size_t)t*BB + b)*HH + n0;
        float4 o0 = {acc[i][0]+ub[0], acc[i][1]+ub[1], acc[i][2]+ub[2], acc[i][3]+ub[3]};
        float4 o1 = {acc[i][4]+ub[4], acc[i][5]+ub[5], acc[i][6]+ub[6], acc[i][7]+ub[7]};
        *(float4*)&g_ux[dst]     = o0;
        *(float4*)&g_ux[dst + 4] = o1;
    }
}

// ============ pack W for the recurrence: g_wP[blk][k][c16] = W[blk*16+c][k] ==
__global__ __launch_bounds__(512) void k_packW(const float* __restrict__ Ww)
{
    __shared__ float tile[32][17];
    const int bx = blockIdx.x;           // k-tile (0..63)
    const int by = blockIdx.y;           // col-block (0..127)
    const int tid = threadIdx.x;
    {
        int c = tid >> 5, kk = tid & 31;
        tile[kk][c] = Ww[(size_t)(by*16 + c)*HH + bx*32 + kk];
    }
    __syncthreads();
    {
        int kk = tid >> 4, c = tid & 15;
        g_wP[(size_t)by*(HH*16) + (size_t)(bx*32 + kk)*16 + c] = tile[kk][c];
    }
}

// ===== pre-round V_w to tf32, store K-permuted within 16-blocks ==============
__global__ __launch_bounds__(256) void k_round_vw(const float* __restrict__ Vw)
{
    size_t i = ((size_t)blockIdx.x*256 + threadIdx.x) * 4;
    float4 v = *(const float4*)&Vw[i];
    float4 o;
    asm("cvt.rna.tf32.f32 %0, %1;" : "=f"(o.x) : "f"(v.x));
    asm("cvt.rna.tf32.f32 %0, %1;" : "=f"(o.y) : "f"(v.y));
    asm("cvt.rna.tf32.f32 %0, %1;" : "=f"(o.z) : "f"(v.z));
    asm("cvt.rna.tf32.f32 %0, %1;" : "=f"(o.w) : "f"(v.w));
    size_t base16 = i & ~(size_t)15;
    size_t q = (i >> 2) & 3;
    g_vw[base16 + q + 0]  = o.x;
    g_vw[base16 + q + 4]  = o.y;
    g_vw[base16 + q + 8]  = o.z;
    g_vw[base16 + q + 12] = o.w;
}

// ============== prologue: h0 fill (graph-replay safe) ========================
__global__ __launch_bounds__(256) void k_rnn_init()
{
    int i = blockIdx.x*256 + threadIdx.x;
    g_hT[0][i] = 0.1f;
}

// ================= one Elman timestep: h_t = tanh(ux_t + W h_{t-1}) ==========
__global__ __launch_bounds__(256, 1) void k_step(int t)
{
    extern __shared__ float sm[];
    float* hs   = sm;            // 2 x [256 k][32 b] = 16384 floats (64 KB)
    float* part = sm + 16384;    // [8][512] = 4096 floats (16 KB)

    const int tid = threadIdx.x;
    const int c2 = tid & 7;
    const int rg = (tid >> 3) & 3;
    const int ks = tid >> 5;                 // warp index = k-slice
    const int cb = blockIdx.x * 16;

    const float4* hsrc = (const float4*)&g_hT[t & 1][0];   // 16384 float4

    // stage chunk 0
    #pragma unroll
    for (int i = 0; i < 8; ++i) {
        int idx = tid + i*256;
        unsigned d = (unsigned)__cvta_generic_to_shared(hs + idx*4);
        asm volatile("cp.async.cg.shared.global [%0], [%1], 16;\n"
                     :: "r"(d), "l"(hsrc + idx));
    }
    asm volatile("cp.async.commit_group;\n");

    unsigned long long a00=0, a01=0, a02=0, a03=0;   // col0 x (b pairs)
    unsigned long long a10=0, a11=0, a12=0, a13=0;   // col1 x (b pairs)

    for (int ch = 0; ch < 8; ++ch) {
        if (ch < 7) {
            float* dst = hs + ((ch+1) & 1)*8192;
            const float4* src = hsrc + (ch+1)*2048;
            #pragma unroll
            for (int i = 0; i < 8; ++i) {
                int idx = tid + i*256;
                unsigned d = (unsigned)__cvta_generic_to_shared(dst + idx*4);
                asm volatile("cp.async.cg.shared.global [%0], [%1], 16;\n"
                             :: "r"(d), "l"(src + idx));
            }
            asm volatile("cp.async.commit_group;\n");
            asm volatile("cp.async.wait_group 1;\n");
        } else {
            asm volatile("cp.async.wait_group 0;\n");
        }
        __syncthreads();

        unsigned hba = (unsigned)__cvta_generic_to_shared(
            hs + (ch & 1)*8192 + (ks*32)*32 + rg*8);
        const float* wp = g_wP + (size_t)blockIdx.x*(HH*16)
                        + (size_t)(ch*256 + ks*32)*16 + c2*2;

        #pragma unroll 8
        for (int kl = 0; kl < 32; ++kl) {
            float2 w = *(const float2*)wp;
            wp += 16;
            unsigned long long w0 = pk2(w.x, w.x);
            unsigned long long w1 = pk2(w.y, w.y);
            unsigned long long h01, h23, h45, h67;
            asm("ld.shared.v2.u64 {%0,%1}, [%2];"
                : "=l"(h01), "=l"(h23) : "r"(hba));
            asm("ld.shared.v2.u64 {%0,%1}, [%2];"
                : "=l"(h45), "=l"(h67) : "r"(hba + 16));
            hba += 128;
            fma2(a00, h01, w0); fma2(a01, h23, w0);
            fma2(a02, h45, w0); fma2(a03, h67, w0);
            fma2(a10, h01, w1); fma2(a11, h23, w1);
            fma2(a12, h45, w1); fma2(a13, h67, w1);
        }
        __syncthreads();
    }

    // scatter partials: part[ks][col(0..15)*32 + b]
    {
        float lo, hi;
        float* p0 = &part[ks*512 + (c2*2 + 0)*32 + rg*8];
        float* p1 = &part[ks*512 + (c2*2 + 1)*32 + rg*8];
        unpk2(a00, lo, hi); p0[0] = lo; p0[1] = hi;
        unpk2(a01, lo, hi); p0[2] = lo; p0[3] = hi;
        unpk2(a02, lo, hi); p0[4] = lo; p0[5] = hi;
        unpk2(a03, lo, hi); p0[6] = lo; p0[7] = hi;
        unpk2(a10, lo, hi); p1[0] = lo; p1[1] = hi;
        unpk2(a11, lo, hi); p1[2] = lo; p1[3] = hi;
        unpk2(a12, lo, hi); p1[4] = lo; p1[5] = hi;
        unpk2(a13, lo, hi); p1[6] = lo; p1[7] = hi;
    }
    __syncthreads();

    // each thread finishes 2 outputs: 8-way k-reduce + ux + tanh + stores
    #pragma unroll
    for (int u = 0; u < 2; ++u) {
        int o = tid*2 + u;                 // 0..511
        int c = o >> 5, b = o & 31;
        float s = part[o] + part[512 + o] + part[1024 + o] + part[1536 + o]
                + part[2048 + o] + part[2560 + o] + part[3072 + o] + part[3584 + o];
        s += g_ux[((size_t)t*BB + b)*HH + cb + c];
        float h = tanhf(s);
        g_hT[(t+1) & 1][(size_t)(cb + c)*BB + b] = h;     // normal order
        float hr; asm("cvt.rna.tf32.f32 %0, %1;" : "=f"(hr) : "f"(h));
        int permc = ((c & 3) << 2) | (c >> 2);            // K-permuted for GEMM
        g_hr[((size_t)b*TT + t)*HH + cb + permc] = hr;
    }
}

// ================= Kernel C: logits = h @ V_w^T + V_b  (tf32 MMA) ============
#define VSTAGE 12288    // floats per stage: A 128x32 (4096) + B 256x32 (8192)
__global__ __launch_bounds__(256, 1) void k_vgemm(const float* __restrict__ Vb,
                                                  float* __restrict__ out)
{
    extern __shared__ float smv[];

    const int bid = blockIdx.x;                 // 8000 = 8 grp x (8 bm x 125 bn)
    const int grp = bid / 1000;
    const int rem = bid % 1000;
    const int bm  = grp*8 + (rem & 7);          // 0..63
    const int bn  = rem >> 3;                   // 0..124

    const int tid = threadIdx.x;
    const int lane = tid & 31, wid = tid >> 5;
    const int wm = (wid >> 2) * 64, wn = (wid & 3) * 64;
    const int gr = lane >> 2, tg = lane & 3;

    const float* Ag = g_hr + (size_t)(bm*128)*HH;
    const float* Bg = g_vw + (size_t)(bn*256)*HH;

    float acc[4][8][4];
    #pragma unroll
    for (int m = 0; m < 4; ++m)
        #pragma unroll
        for (int n = 0; n < 8; ++n)
            #pragma unroll
            for (int q = 0; q < 4; ++q) acc[m][n][q] = 0.f;

    auto stage_load = [&](int c, int s) {
        float* As = smv + s*VSTAGE;
        float* Bs = As + 4096;
        #pragma unroll
        for (int i = 0; i < 4; ++i) {             // A: 1024 x 16B
            int o = tid + i*256;
            int kg = o >> 9, row = (o >> 2) & 127, q = o & 3;
            unsigned d = (unsigned)__cvta_generic_to_shared(As + o*4);
            const float* src = Ag + (size_t)row*HH + c*32 + kg*16 + q*4;
            asm volatile("cp.async.cg.shared.global [%0], [%1], 16;\n"
                         :: "r"(d), "l"(src));
        }
        #pragma unroll
        for (int i = 0; i < 8; ++i) {             // B: 2048 x 16B
            int o = tid + i*256;
            int kg = o >> 10, row = (o >> 2) & 255, q = o & 3;
            unsigned d = (unsigned)__cvta_generic_to_shared(Bs + o*4);
            const float* src = Bg + (size_t)row*HH + c*32 + kg*16 + q*4;
            asm volatile("cp.async.cg.shared.global [%0], [%1], 16;\n"
                         :: "r"(d), "l"(src));
        }
        asm volatile("cp.async.commit_group;\n");
    };

    stage_load(0, 0);
    stage_load(1, 1);

    int sc = 0, sl = 2;
    const int NCH = HH/32;                        // 64 chunks
    for (int c = 0; c < NCH; ++c) {
        if (c < NCH-1) asm volatile("cp.async.wait_group 1;\n");
        else           asm volatile("cp.async.wait_group 0;\n");
        __syncthreads();
        if (c + 2 < NCH) {
            stage_load(c + 2, sl);
            sl = (sl == 2) ? 0 : sl + 1;
        }

        const float* As = smv + sc*VSTAGE;
        const float* Bs = As + 4096;
        #pragma unroll
        for (int kg = 0; kg < 2; ++kg) {
            float4 af[4][2]; float4 bf[8];
            #pragma unroll
            for (int mt = 0; mt < 4; ++mt) {
                af[mt][0] = *(const float4*)&As[(kg*128 + wm + mt*16 + gr)*16 + tg*4];
                af[mt][1] = *(const float4*)&As[(kg*128 + wm + mt*16 + 8 + gr)*16 + tg*4];
            }
            #pragma unroll
            for (int nt = 0; nt < 8; ++nt)
                bf[nt] = *(const float4*)&Bs[(kg*256 + wn + nt*8 + gr)*16 + tg*4];

            #pragma unroll
            for (int mt = 0; mt < 4; ++mt)
                #pragma unroll
                for (int nt = 0; nt < 8; ++nt) {
                    asm volatile(
                        "mma.sync.aligned.m16n8k8.row.col.f32.tf32.tf32.f32 "
                        "{%0,%1,%2,%3},{%4,%5,%6,%7},{%8,%9},{%0,%1,%2,%3};\n"
                        : "+f"(acc[mt][nt][0]), "+f"(acc[mt][nt][1]),
                          "+f"(acc[mt][nt][2]), "+f"(acc[mt][nt][3])
                        : "r"(__float_as_uint(af[mt][0].x)), "r"(__float_as_uint(af[mt][1].x)),
                          "r"(__float_as_uint(af[mt][0].y)), "r"(__float_as_uint(af[mt][1].y)),
                          "r"(__float_as_uint(bf[nt].x)),    "r"(__float_as_uint(bf[nt].y)));
                    asm volatile(
                        "mma.sync.aligned.m16n8k8.row.col.f32.tf32.tf32.f32 "
                        "{%0,%1,%2,%3},{%4,%5,%6,%7},{%8,%9},{%0,%1,%2,%3};\n"
                        : "+f"(acc[mt][nt][0]), "+f"(acc[mt][nt][1]),
                          "+f"(acc[mt][nt][2]), "+f"(acc[mt][nt][3])
                        : "r"(__float_as_uint(af[mt][0].z)), "r"(__float_as_uint(af[mt][1].z)),
                          "r"(__float_as_uint(af[mt][0].w)), "r"(__float_as_uint(af[mt][1].w)),
                          "r"(__float_as_uint(bf[nt].z)),    "r"(__float_as_uint(bf[nt].w)));
                }
        }
        sc = (sc == 2) ? 0 : sc + 1;
    }

    // epilogue: +bias, store fp32 logits
    #pragma unroll
    for (int mt = 0; mt < 4; ++mt) {
        size_t r0 = (size_t)(bm*128 + wm + mt*16 + gr);
        #pragma unroll
        for (int nt = 0; nt < 8; ++nt) {
            int col = bn*256 + wn + nt*8 + tg*2;
            float b0 = Vb[col], b1 = Vb[col+1];
            float2 v0 = {acc[mt][nt][0] + b0, acc[mt][nt][1] + b1};
            float2 v1 = {acc[mt][nt][2] + b0, acc[mt][nt][3] + b1};
            *(float2*)&out[r0*VV + col]       = v0;
            *(float2*)&out[(r0+8)*VV + col]   = v1;
        }
    }
}

// ====== Kernel D1: log-softmax loss via f16x2 ex2 (no max pass needed) =======
// logits ~ N(0,1) (max ~6; inf needs logit > 16.6 = 16 sigma). y = x*log2e - 8
// keeps all realistic values in f16 range; sum in fp32; lse = (log2(S)+8)*ln2.
__global__ __launch_bounds__(256) void k_rowloss(const float* __restrict__ logits,
                                                 const int* __restrict__ targets)
{
    __shared__ float ssm[256];
    const int r = blockIdx.x;
    const int tid = threadIdx.x;
    const float4* row4 = (const float4*)(logits + (size_t)r*VV);
    const float C = 1.4426950408889634f;   // log2(e)

    float s0 = 0.f, s1 = 0.f;
    for (int i = tid; i < VV/4; i += 256) {
        float4 v = row4[i];
        float y0 = fmaf(v.x, C, -8.f);
        float y1 = fmaf(v.y, C, -8.f);
        float y2 = fmaf(v.z, C, -8.f);
        float y3 = fmaf(v.w, C, -8.f);
        uint32_t h01, h23, e01, e23;
        asm("cvt.rn.f16x2.f32 %0, %1, %2;" : "=r"(h01) : "f"(y1), "f"(y0));
        asm("cvt.rn.f16x2.f32 %0, %1, %2;" : "=r"(h23) : "f"(y3), "f"(y2));
        asm("ex2.approx.f16x2 %0, %1;" : "=r"(e01) : "r"(h01));
        asm("ex2.approx.f16x2 %0, %1;" : "=r"(e23) : "r"(h23));
        float a, b, c2, d;
        asm("{.reg .f16 l,h; mov.b32 {l,h}, %2; cvt.f32.f16 %0, l; cvt.f32.f16 %1, h;}"
            : "=f"(a), "=f"(b) : "r"(e01));
        asm("{.reg .f16 l,h; mov.b32 {l,h}, %2; cvt.f32.f16 %0, l; cvt.f32.f16 %1, h;}"
            : "=f"(c2), "=f"(d) : "r"(e23));
        s0 += a + b;
        s1 += c2 + d;
    }
    ssm[tid] = s0 + s1;
    __syncthreads();
    for (int st = 128; st > 0; st >>= 1) {
        if (tid < st) ssm[tid] += ssm[tid + st];
        __syncthreads();
    }
    if (tid == 0) {
        float lse = (__log2f(ssm[0]) + 8.f) * 0.6931471805599453f;
        g_rowloss[r] = lse - logits[(size_t)r*VV + targets[r]];
    }
}

// ================= Kernel D2: mean of row losses -> d_out[last] ==============
__global__ __launch_bounds__(256) void k_loss(float* __restrict__ out, int out_size)
{
    __shared__ float red[256];
    const int tid = threadIdx.x;
    float s = 0.f;
    for (int i = tid; i < BT; i += 256) s += g_rowloss[i];
    red[tid] = s; __syncthreads();
    for (int st = 128; st > 0; st >>= 1) {
        if (tid < st) red[tid] += red[tid+st];
        __syncthreads();
    }
    if (tid == 0) out[(size_t)out_size - 1] = red[0] / (float)BT;
}

// ============================== launch =======================================
extern "C" void kernel_launch(void* const* d_in, const int* in_sizes, int n_in,
                              void* d_out, int out_size)
{
    const int*   xb      = (const int*)  d_in[0];
    const int*   targets = (const int*)  d_in[1];
    const float* Cemb    = (const float*)d_in[2];
    const float* Uw      = (const float*)d_in[3];
    const float* Ub      = (const float*)d_in[4];
    const float* Ww      = (const float*)d_in[5];
    const float* Vw      = (const float*)d_in[6];
    const float* Vb      = (const float*)d_in[7];
    float* out = (float*)d_out;

    // order chosen so the ncu capture slot (4th launch) lands on k_step t=0
    k_uproj<<<dim3(16, 64), 256>>>(xb, Cemb, Uw, Ub);       // 1
    k_rnn_init<<<256, 256>>>();                              // 2
    k_packW<<<dim3(64, 128), 512>>>(Ww);                     // 3

    // recurrence: one kernel per step (kernel boundary = barrier; no spin)
    cudaFuncSetAttribute((const void*)k_step,
                         cudaFuncAttributeMaxDynamicSharedMemorySize, 81920);
    for (int t = 0; t < TT; ++t) {
        k_step<<<128, 256, 81920>>>(t);                      // 4 .. 259
    }

    // tf32 prep for V (only needed by vgemm; after recurrence on purpose)
    k_round_vw<<<64000, 256>>>(Vw);

    // big vocab GEMM on tensor cores (tf32, vectorized frag loads, 3-stage)
    cudaFuncSetAttribute((const void*)k_vgemm,
                         cudaFuncAttributeMaxDynamicSharedMemorySize, 3*VSTAGE*4);
    k_vgemm<<<8000, 256, 3*VSTAGE*4>>>(Vb, out);

    // loss
    k_rowloss<<<BT, 256>>>(out, targets);
    k_loss<<<1, 256>>>(out, out_size);
}

// round 13
// speedup vs baseline: 1.2837x; 1.0471x over previous
#include <cuda_runtime.h>
#include <cstdint>
#include <math.h>

#define BB 32
#define TT 256
#define DD 512
#define HH 2048
#define VV 32000
#define BT (BB*TT)          // 8192

// ---------------- scratch (device globals; no allocation allowed) ------------
__device__ float g_ux[BT*HH];            // [T][B][H] input projection
__device__ float g_hr[BT*HH];            // [B,T,H] tf32 h, K-permuted in 16-blk
__device__ float g_hT[2][HH*BB];         // transposed h double buffer [k][b]
__device__ float g_wP[(size_t)HH*HH];    // W packed: [blk][k][16 cols]
__device__ float g_vw[(size_t)VV*HH];    // tf32 V_w, K-permuted in 16-blk
__device__ float g_rowloss[BT];

// ---------------- f32x2 packed helpers --------------------------------------
__device__ __forceinline__ unsigned long long pk2(float a, float b) {
    unsigned long long r;
    asm("mov.b64 %0, {%1, %2};" : "=l"(r) : "f"(a), "f"(b));
    return r;
}
__device__ __forceinline__ void fma2(unsigned long long& acc,
                                     unsigned long long a, unsigned long long b) {
    asm("fma.rn.f32x2 %0, %1, %2, %0;" : "+l"(acc) : "l"(a), "l"(b));
}
__device__ __forceinline__ void unpk2(unsigned long long v, float& lo, float& hi) {
    asm("mov.b64 {%0, %1}, %2;" : "=f"(lo), "=f"(hi) : "l"(v));
}

// ======================= Kernel A: ux = C[xb] @ U^T + b ======================
__global__ __launch_bounds__(256) void k_uproj(const int* __restrict__ xb,
                                               const float* __restrict__ Cemb,
                                               const float* __restrict__ Uw,
                                               const float* __restrict__ Ub)
{
    __shared__ float As[16][128];
    __shared__ float Bs[16][128];
    const int bn = blockIdx.x, bm = blockIdx.y;
    const int tid = threadIdx.x;
    const int tx = tid & 15, ty = tid >> 4;

    float acc[8][8];
    #pragma unroll
    for (int i = 0; i < 8; ++i)
        #pragma unroll
        for (int j = 0; j < 8; ++j) acc[i][j] = 0.f;

    for (int c = 0; c < DD/16; ++c) {
        const int k0 = c * 16;
        #pragma unroll
        for (int it = 0; it < 2; ++it) {
            int idx = tid + it*256;
            int r = idx & 127, q = idx >> 7;
            int tok = xb[bm*128 + r];
            float4 v = *(const float4*)&Cemb[(size_t)tok*DD + k0 + q*4];
            As[q*4+0][r] = v.x; As[q*4+1][r] = v.y;
            As[q*4+2][r] = v.z; As[q*4+3][r] = v.w;
        }
        #pragma unroll
        for (int it = 0; it < 2; ++it) {
            int idx = tid + it*256;
            int r = idx & 127, q = idx >> 7;
            float4 v = *(const float4*)&Uw[(size_t)(bn*128 + r)*DD + k0 + q*4];
            Bs[q*4+0][r] = v.x; Bs[q*4+1][r] = v.y;
            Bs[q*4+2][r] = v.z; Bs[q*4+3][r] = v.w;
        }
        __syncthreads();
        #pragma unroll
        for (int k = 0; k < 16; ++k) {
            float a[8], b[8];
            *(float4*)(a)   = *(float4*)&As[k][ty*8];
            *(float4*)(a+4) = *(float4*)&As[k][ty*8+4];
            *(float4*)(b)   = *(float4*)&Bs[k][tx*8];
            *(float4*)(b+4) = *(float4*)&Bs[k][tx*8+4];
            #pragma unroll
            for (int i = 0; i < 8; ++i)
                #pragma unroll
                for (int j = 0; j < 8; ++j) acc[i][j] += a[i]*b[j];
        }
        __syncthreads();
    }
    const int n0 = bn*128 + tx*8;
    float ub[8];
    #pragma unroll
    for (int j = 0; j < 8; ++j) ub[j] = Ub[n0+j];
    #pragma unroll
    for (int i = 0; i < 8; ++i) {
        int m = bm*128 + ty*8 + i;       // m = b*TT + t
        int t = m & 255, b = m >> 8;
        size_t dst = ((size_t)t*BB + b)*HH + n0;
        float4 o0 = {acc[i][0]+ub[0], acc[i][1]+ub[1], acc[i][2]+ub[2], acc[i][3]+ub[3]};
        float4 o1 = {acc[i][4]+ub[4], acc[i][5]+ub[5], acc[i][6]+ub[6], acc[i][7]+ub[7]};
        *(float4*)&g_ux[dst]     = o0;
        *(float4*)&g_ux[dst + 4] = o1;
    }
}

// ============ pack W for the recurrence: g_wP[blk][k][c16] = W[blk*16+c][k] ==
__global__ __launch_bounds__(512) void k_packW(const float* __restrict__ Ww)
{
    __shared__ float tile[32][17];
    const int bx = blockIdx.x;           // k-tile (0..63)
    const int by = blockIdx.y;           // col-block (0..127)
    const int tid = threadIdx.x;
    {
        int c = tid >> 5, kk = tid & 31;
        tile[kk][c] = Ww[(size_t)(by*16 + c)*HH + bx*32 + kk];
    }
    __syncthreads();
    {
        int kk = tid >> 4, c = tid & 15;
        g_wP[(size_t)by*(HH*16) + (size_t)(bx*32 + kk)*16 + c] = tile[kk][c];
    }
}

// ===== pre-round V_w to tf32, store K-permuted within 16-blocks ==============
__global__ __launch_bounds__(256) void k_round_vw(const float* __restrict__ Vw)
{
    size_t i = ((size_t)blockIdx.x*256 + threadIdx.x) * 4;
    float4 v = *(const float4*)&Vw[i];
    float4 o;
    asm("cvt.rna.tf32.f32 %0, %1;" : "=f"(o.x) : "f"(v.x));
    asm("cvt.rna.tf32.f32 %0, %1;" : "=f"(o.y) : "f"(v.y));
    asm("cvt.rna.tf32.f32 %0, %1;" : "=f"(o.z) : "f"(v.z));
    asm("cvt.rna.tf32.f32 %0, %1;" : "=f"(o.w) : "f"(v.w));
    size_t base16 = i & ~(size_t)15;
    size_t q = (i >> 2) & 3;
    g_vw[base16 + q + 0]  = o.x;
    g_vw[base16 + q + 4]  = o.y;
    g_vw[base16 + q + 8]  = o.z;
    g_vw[base16 + q + 12] = o.w;
}

// ============== prologue: h0 fill (graph-replay safe) ========================
__global__ __launch_bounds__(256) void k_rnn_init()
{
    int i = blockIdx.x*256 + threadIdx.x;
    g_hT[0][i] = 0.1f;
}

// ================= one Elman timestep: h_t = tanh(ux_t + W h_{t-1}) ==========
// grid 128 x 256 thr. Block owns 16 H-cols over full K=2048.
// BOTH h (32KB) and W (16KB) chunks are cp.async double-buffered into smem —
// no latency-exposed global loads in the compute loop at all.
__global__ __launch_bounds__(256, 1) void k_step(int t)
{
    extern __shared__ float sm[];
    float* hs   = sm;            // 2 x [256 k][32 b] = 16384 floats (64 KB)
    float* ws   = sm + 16384;    // 2 x [256 k][16 c] =  8192 floats (32 KB)
    float* part = sm + 24576;    // [8][512]          =  4096 floats (16 KB)

    const int tid = threadIdx.x;
    const int c2 = tid & 7;
    const int rg = (tid >> 3) & 3;
    const int ks = tid >> 5;                 // warp index = k-slice
    const int cb = blockIdx.x * 16;

    const float4* hsrc = (const float4*)&g_hT[t & 1][0];   // 16384 float4
    const float4* wsrc = (const float4*)(g_wP + (size_t)blockIdx.x*(HH*16));

    auto stage = [&](int c, int s) {
        // h chunk: 2048 float4
        float* hd = hs + s*8192;
        #pragma unroll
        for (int i = 0; i < 8; ++i) {
            int idx = tid + i*256;
            unsigned d = (unsigned)__cvta_generic_to_shared(hd + idx*4);
            asm volatile("cp.async.cg.shared.global [%0], [%1], 16;\n"
                         :: "r"(d), "l"(hsrc + c*2048 + idx));
        }
        // W chunk: 1024 float4
        float* wd = ws + s*4096;
        #pragma unroll
        for (int i = 0; i < 4; ++i) {
            int idx = tid + i*256;
            unsigned d = (unsigned)__cvta_generic_to_shared(wd + idx*4);
            asm volatile("cp.async.cg.shared.global [%0], [%1], 16;\n"
                         :: "r"(d), "l"(wsrc + c*1024 + idx));
        }
        asm volatile("cp.async.commit_group;\n");
    };

    stage(0, 0);

    unsigned long long a00=0, a01=0, a02=0, a03=0;   // col0 x (b pairs)
    unsigned long long a10=0, a11=0, a12=0, a13=0;   // col1 x (b pairs)

    for (int ch = 0; ch < 8; ++ch) {
        if (ch < 7) {
            stage(ch + 1, (ch + 1) & 1);
            asm volatile("cp.async.wait_group 1;\n");
        } else {
            asm volatile("cp.async.wait_group 0;\n");
        }
        __syncthreads();

        unsigned hba = (unsigned)__cvta_generic_to_shared(
            hs + (ch & 1)*8192 + (ks*32)*32 + rg*8);
        unsigned wba = (unsigned)__cvta_generic_to_shared(
            ws + (ch & 1)*4096 + (ks*32)*16 + c2*2);

        #pragma unroll 8
        for (int kl = 0; kl < 32; ++kl) {
            float wx, wy;
            asm("ld.shared.v2.f32 {%0, %1}, [%2];" : "=f"(wx), "=f"(wy) : "r"(wba));
            wba += 64;
            unsigned long long w0 = pk2(wx, wx);
            unsigned long long w1 = pk2(wy, wy);
            unsigned long long h01, h23, h45, h67;
            asm("ld.shared.v2.u64 {%0,%1}, [%2];"
                : "=l"(h01), "=l"(h23) : "r"(hba));
            asm("ld.shared.v2.u64 {%0,%1}, [%2];"
                : "=l"(h45), "=l"(h67) : "r"(hba + 16));
            hba += 128;
            fma2(a00, h01, w0); fma2(a01, h23, w0);
            fma2(a02, h45, w0); fma2(a03, h67, w0);
            fma2(a10, h01, w1); fma2(a11, h23, w1);
            fma2(a12, h45, w1); fma2(a13, h67, w1);
        }
        __syncthreads();
    }

    // scatter partials: part[ks][col(0..15)*32 + b]
    {
        float lo, hi;
        float* p0 = &part[ks*512 + (c2*2 + 0)*32 + rg*8];
        float* p1 = &part[ks*512 + (c2*2 + 1)*32 + rg*8];
        unpk2(a00, lo, hi); p0[0] = lo; p0[1] = hi;
        unpk2(a01, lo, hi); p0[2] = lo; p0[3] = hi;
        unpk2(a02, lo, hi); p0[4] = lo; p0[5] = hi;
        unpk2(a03, lo, hi); p0[6] = lo; p0[7] = hi;
        unpk2(a10, lo, hi); p1[0] = lo; p1[1] = hi;
        unpk2(a11, lo, hi); p1[2] = lo; p1[3] = hi;
        unpk2(a12, lo, hi); p1[4] = lo; p1[5] = hi;
        unpk2(a13, lo, hi); p1[6] = lo; p1[7] = hi;
    }
    __syncthreads();

    // each thread finishes 2 outputs: 8-way k-reduce + ux + tanh + stores
    #pragma unroll
    for (int u = 0; u < 2; ++u) {
        int o = tid*2 + u;                 // 0..511
        int c = o >> 5, b = o & 31;
        float s = part[o] + part[512 + o] + part[1024 + o] + part[1536 + o]
                + part[2048 + o] + part[2560 + o] + part[3072 + o] + part[3584 + o];
        s += g_ux[((size_t)t*BB + b)*HH + cb + c];
        float h = tanhf(s);
        g_hT[(t+1) & 1][(size_t)(cb + c)*BB + b] = h;     // normal order
        float hr; asm("cvt.rna.tf32.f32 %0, %1;" : "=f"(hr) : "f"(h));
        int permc = ((c & 3) << 2) | (c >> 2);            // K-permuted for GEMM
        g_hr[((size_t)b*TT + t)*HH + cb + permc] = hr;
    }
}

// ================= Kernel C: logits = h @ V_w^T + V_b  (tf32 MMA) ============
#define VSTAGE 12288    // floats per stage: A 128x32 (4096) + B 256x32 (8192)
__global__ __launch_bounds__(256, 1) void k_vgemm(const float* __restrict__ Vb,
                                                  float* __restrict__ out)
{
    extern __shared__ float smv[];

    const int bid = blockIdx.x;                 // 8000 = 8 grp x (8 bm x 125 bn)
    const int grp = bid / 1000;
    const int rem = bid % 1000;
    const int bm  = grp*8 + (rem & 7);          // 0..63
    const int bn  = rem >> 3;                   // 0..124

    const int tid = threadIdx.x;
    const int lane = tid & 31, wid = tid >> 5;
    const int wm = (wid >> 2) * 64, wn = (wid & 3) * 64;
    const int gr = lane >> 2, tg = lane & 3;

    const float* Ag = g_hr + (size_t)(bm*128)*HH;
    const float* Bg = g_vw + (size_t)(bn*256)*HH;

    float acc[4][8][4];
    #pragma unroll
    for (int m = 0; m < 4; ++m)
        #pragma unroll
        for (int n = 0; n < 8; ++n)
            #pragma unroll
            for (int q = 0; q < 4; ++q) acc[m][n][q] = 0.f;

    auto stage_load = [&](int c, int s) {
        float* As = smv + s*VSTAGE;
        float* Bs = As + 4096;
        #pragma unroll
        for (int i = 0; i < 4; ++i) {             // A: 1024 x 16B
            int o = tid + i*256;
            int kg = o >> 9, row = (o >> 2) & 127, q = o & 3;
            unsigned d = (unsigned)__cvta_generic_to_shared(As + o*4);
            const float* src = Ag + (size_t)row*HH + c*32 + kg*16 + q*4;
            asm volatile("cp.async.cg.shared.global [%0], [%1], 16;\n"
                         :: "r"(d), "l"(src));
        }
        #pragma unroll
        for (int i = 0; i < 8; ++i) {             // B: 2048 x 16B
            int o = tid + i*256;
            int kg = o >> 10, row = (o >> 2) & 255, q = o & 3;
            unsigned d = (unsigned)__cvta_generic_to_shared(Bs + o*4);
            const float* src = Bg + (size_t)row*HH + c*32 + kg*16 + q*4;
            asm volatile("cp.async.cg.shared.global [%0], [%1], 16;\n"
                         :: "r"(d), "l"(src));
        }
        asm volatile("cp.async.commit_group;\n");
    };

    stage_load(0, 0);
    stage_load(1, 1);

    int sc = 0, sl = 2;
    const int NCH = HH/32;                        // 64 chunks
    for (int c = 0; c < NCH; ++c) {
        if (c < NCH-1) asm volatile("cp.async.wait_group 1;\n");
        else           asm volatile("cp.async.wait_group 0;\n");
        __syncthreads();
        if (c + 2 < NCH) {
            stage_load(c + 2, sl);
            sl = (sl == 2) ? 0 : sl + 1;
        }

        const float* As = smv + sc*VSTAGE;
        const float* Bs = As + 4096;
        #pragma unroll
        for (int kg = 0; kg < 2; ++kg) {
            float4 af[4][2]; float4 bf[8];
            #pragma unroll
            for (int mt = 0; mt < 4; ++mt) {
                af[mt][0] = *(const float4*)&As[(kg*128 + wm + mt*16 + gr)*16 + tg*4];
                af[mt][1] = *(const float4*)&As[(kg*128 + wm + mt*16 + 8 + gr)*16 + tg*4];
            }
            #pragma unroll
            for (int nt = 0; nt < 8; ++nt)
                bf[nt] = *(const float4*)&Bs[(kg*256 + wn + nt*8 + gr)*16 + tg*4];

            #pragma unroll
            for (int mt = 0; mt < 4; ++mt)
                #pragma unroll
                for (int nt = 0; nt < 8; ++nt) {
                    asm volatile(
                        "mma.sync.aligned.m16n8k8.row.col.f32.tf32.tf32.f32 "
                        "{%0,%1,%2,%3},{%4,%5,%6,%7},{%8,%9},{%0,%1,%2,%3};\n"
                        : "+f"(acc[mt][nt][0]), "+f"(acc[mt][nt][1]),
                          "+f"(acc[mt][nt][2]), "+f"(acc[mt][nt][3])
                        : "r"(__float_as_uint(af[mt][0].x)), "r"(__float_as_uint(af[mt][1].x)),
                          "r"(__float_as_uint(af[mt][0].y)), "r"(__float_as_uint(af[mt][1].y)),
                          "r"(__float_as_uint(bf[nt].x)),    "r"(__float_as_uint(bf[nt].y)));
                    asm volatile(
                        "mma.sync.aligned.m16n8k8.row.col.f32.tf32.tf32.f32 "
                        "{%0,%1,%2,%3},{%4,%5,%6,%7},{%8,%9},{%0,%1,%2,%3};\n"
                        : "+f"(acc[mt][nt][0]), "+f"(acc[mt][nt][1]),
                          "+f"(acc[mt][nt][2]), "+f"(acc[mt][nt][3])
                        : "r"(__float_as_uint(af[mt][0].z)), "r"(__float_as_uint(af[mt][1].z)),
                          "r"(__float_as_uint(af[mt][0].w)), "r"(__float_as_uint(af[mt][1].w)),
                          "r"(__float_as_uint(bf[nt].z)),    "r"(__float_as_uint(bf[nt].w)));
                }
        }
        sc = (sc == 2) ? 0 : sc + 1;
    }

    // epilogue: +bias, store fp32 logits
    #pragma unroll
    for (int mt = 0; mt < 4; ++mt) {
        size_t r0 = (size_t)(bm*128 + wm + mt*16 + gr);
        #pragma unroll
        for (int nt = 0; nt < 8; ++nt) {
            int col = bn*256 + wn + nt*8 + tg*2;
            float b0 = Vb[col], b1 = Vb[col+1];
            float2 v0 = {acc[mt][nt][0] + b0, acc[mt][nt][1] + b1};
            float2 v1 = {acc[mt][nt][2] + b0, acc[mt][nt][3] + b1};
            *(float2*)&out[r0*VV + col]       = v0;
            *(float2*)&out[(r0+8)*VV + col]   = v1;
        }
    }
}

// ====== Kernel D1: log-softmax loss via f16x2 ex2 (no max pass needed) =======
__global__ __launch_bounds__(256) void k_rowloss(const float* __restrict__ logits,
                                                 const int* __restrict__ targets)
{
    __shared__ float ssm[256];
    const int r = blockIdx.x;
    const int tid = threadIdx.x;
    const float4* row4 = (const float4*)(logits + (size_t)r*VV);
    const float C = 1.4426950408889634f;   // log2(e)

    float s0 = 0.f, s1 = 0.f;
    for (int i = tid; i < VV/4; i += 256) {
        float4 v = row4[i];
        float y0 = fmaf(v.x, C, -8.f);
        float y1 = fmaf(v.y, C, -8.f);
        float y2 = fmaf(v.z, C, -8.f);
        float y3 = fmaf(v.w, C, -8.f);
        uint32_t h01, h23, e01, e23;
        asm("cvt.rn.f16x2.f32 %0, %1, %2;" : "=r"(h01) : "f"(y1), "f"(y0));
        asm("cvt.rn.f16x2.f32 %0, %1, %2;" : "=r"(h23) : "f"(y3), "f"(y2));
        asm("ex2.approx.f16x2 %0, %1;" : "=r"(e01) : "r"(h01));
        asm("ex2.approx.f16x2 %0, %1;" : "=r"(e23) : "r"(h23));
        float a, b, c2, d;
        asm("{.reg .f16 l,h; mov.b32 {l,h}, %2; cvt.f32.f16 %0, l; cvt.f32.f16 %1, h;}"
            : "=f"(a), "=f"(b) : "r"(e01));
        asm("{.reg .f16 l,h; mov.b32 {l,h}, %2; cvt.f32.f16 %0, l; cvt.f32.f16 %1, h;}"
            : "=f"(c2), "=f"(d) : "r"(e23));
        s0 += a + b;
        s1 += c2 + d;
    }
    ssm[tid] = s0 + s1;
    __syncthreads();
    for (int st = 128; st > 0; st >>= 1) {
        if (tid < st) ssm[tid] += ssm[tid + st];
        __syncthreads();
    }
    if (tid == 0) {
        float lse = (__log2f(ssm[0]) + 8.f) * 0.6931471805599453f;
        g_rowloss[r] = lse - logits[(size_t)r*VV + targets[r]];
    }
}

// ================= Kernel D2: mean of row losses -> d_out[last] ==============
__global__ __launch_bounds__(256) void k_loss(float* __restrict__ out, int out_size)
{
    __shared__ float red[256];
    const int tid = threadIdx.x;
    float s = 0.f;
    for (int i = tid; i < BT; i += 256) s += g_rowloss[i];
    red[tid] = s; __syncthreads();
    for (int st = 128; st > 0; st >>= 1) {
        if (tid < st) red[tid] += red[tid+st];
        __syncthreads();
    }
    if (tid == 0) out[(size_t)out_size - 1] = red[0] / (float)BT;
}

// ============================== launch =======================================
extern "C" void kernel_launch(void* const* d_in, const int* in_sizes, int n_in,
                              void* d_out, int out_size)
{
    const int*   xb      = (const int*)  d_in[0];
    const int*   targets = (const int*)  d_in[1];
    const float* Cemb    = (const float*)d_in[2];
    const float* Uw      = (const float*)d_in[3];
    const float* Ub      = (const float*)d_in[4];
    const float* Ww      = (const float*)d_in[5];
    const float* Vw      = (const float*)d_in[6];
    const float* Vb      = (const float*)d_in[7];
    float* out = (float*)d_out;

    // order: ncu skips 5 launches -> capture lands on k_step t=1 (steady state)
    k_uproj<<<dim3(16, 64), 256>>>(xb, Cemb, Uw, Ub);       // 1
    k_rnn_init<<<256, 256>>>();                              // 2
    k_packW<<<dim3(64, 128), 512>>>(Ww);                     // 3
    k_round_vw<<<64000, 256>>>(Vw);                          // 4

    // recurrence: one kernel per step (kernel boundary = barrier; no spin)
    cudaFuncSetAttribute((const void*)k_step,
                         cudaFuncAttributeMaxDynamicSharedMemorySize, 114688);
    for (int t = 0; t < TT; ++t) {
        k_step<<<128, 256, 114688>>>(t);                     // 5 .. 260
    }

    // big vocab GEMM on tensor cores (tf32, vectorized frag loads, 3-stage)
    cudaFuncSetAttribute((const void*)k_vgemm,
                         cudaFuncAttributeMaxDynamicSharedMemorySize, 3*VSTAGE*4);
    k_vgemm<<<8000, 256, 3*VSTAGE*4>>>(Vb, out);

    // loss
    k_rowloss<<<BT, 256>>>(out, targets);
    k_loss<<<1, 256>>>(out, out_size);
}